// round 4
// baseline (speedup 1.0000x reference)
#include <cuda_runtime.h>
#include <math.h>

// Problem constants
#define BATCH  2
#define SEQ    2048
#define NHEADS 16
#define DMODEL 1024
#define DHEAD  64
#define MROWS  (BATCH*SEQ)   // 4096

// Scratch (allocation-free: __device__ globals). 4 x 16 MB.
__device__ float g_Q[(size_t)MROWS * DMODEL];
__device__ float g_K[(size_t)MROWS * DMODEL];
__device__ float g_V[(size_t)MROWS * DMODEL];
__device__ float g_Z[(size_t)MROWS * DMODEL];

// ---------------------------------------------------------------------------
// Kernel 1: fused QKV projection.
//   out[m, h*64+e] = (sum_k x[m,k] * W[h,k,e] + b[h,e]) * (scale if Q)
// Tile: BM=64, BN=64(=one head), BK=16. 256 threads, 4x4 micro-tile.
// grid = (16 n-tiles, 64 m-tiles, 3 matrices)
// ---------------------------------------------------------------------------
__global__ __launch_bounds__(256) void qkv_kernel(
    const float* __restrict__ x,
    const float* __restrict__ Wq, const float* __restrict__ Wk,
    const float* __restrict__ Wv,
    const float* __restrict__ bq, const float* __restrict__ bk,
    const float* __restrict__ bv)
{
    const int mat = blockIdx.z;              // 0=Q, 1=K, 2=V
    const int nt  = blockIdx.x;              // head index (BN=64=DHEAD)
    const int mt  = blockIdx.y;

    const float* W    = (mat == 0) ? Wq : (mat == 1) ? Wk : Wv;
    const float* bias = (mat == 0) ? bq : (mat == 1) ? bk : bv;
    float*       out  = (mat == 0) ? g_Q : (mat == 1) ? g_K : g_V;

    __shared__ float As[16][68];   // A transposed [k][m], pad to kill 4-way store conflicts
    __shared__ float Bs[16][64];   // [k][n]

    const int tid = threadIdx.x;
    const int tx  = tid & 15;
    const int ty  = tid >> 4;
    const int m0  = mt * 64;

    const float* Wh = W + (size_t)nt * (DMODEL * DHEAD);

    // loader indices
    const int la_m  = tid >> 2;            // 0..63
    const int la_k4 = (tid & 3) * 4;       // 0,4,8,12
    const int lb_k  = tid >> 4;            // 0..15
    const int lb_n4 = (tid & 15) * 4;      // 0..60

    float acc[4][4] = {};

    for (int k0 = 0; k0 < DMODEL; k0 += 16) {
        float4 av = *(const float4*)(x + (size_t)(m0 + la_m) * DMODEL + k0 + la_k4);
        As[la_k4 + 0][la_m] = av.x;
        As[la_k4 + 1][la_m] = av.y;
        As[la_k4 + 2][la_m] = av.z;
        As[la_k4 + 3][la_m] = av.w;
        *(float4*)&Bs[lb_k][lb_n4] =
            *(const float4*)(Wh + (size_t)(k0 + lb_k) * DHEAD + lb_n4);
        __syncthreads();

        #pragma unroll
        for (int kk = 0; kk < 16; kk++) {
            float ra[4], rb[4];
            #pragma unroll
            for (int i = 0; i < 4; i++) ra[i] = As[kk][ty * 4 + i];
            #pragma unroll
            for (int j = 0; j < 4; j++) rb[j] = Bs[kk][tx * 4 + j];
            #pragma unroll
            for (int i = 0; i < 4; i++)
                #pragma unroll
                for (int j = 0; j < 4; j++)
                    acc[i][j] = fmaf(ra[i], rb[j], acc[i][j]);
        }
        __syncthreads();
    }

    const float qscale = (mat == 0) ? 0.125f : 1.0f;   // 1/sqrt(64), applied to (xW+b)
    const int   n0     = nt * 64;
    #pragma unroll
    for (int i = 0; i < 4; i++) {
        const int m = m0 + ty * 4 + i;
        #pragma unroll
        for (int j = 0; j < 4; j++) {
            const int n = n0 + tx * 4 + j;
            out[(size_t)m * DMODEL + n] = (acc[i][j] + bias[n]) * qscale;
        }
    }
}

// ---------------------------------------------------------------------------
// Kernel 2: causal flash attention per (b, h, 64-query tile).
// Q pre-scaled. Online softmax, 4x4 register micro-tiles for both GEMMs.
// Dynamic smem: Qs/Ks/Vs/Ps each 64x65 floats = 66560 B.
// grid = (SEQ/64, NHEADS, BATCH), 256 threads
// ---------------------------------------------------------------------------
__global__ __launch_bounds__(256) void attn_kernel()
{
    extern __shared__ float sm[];
    float* Qs = sm;                // [64][65]
    float* Ks = Qs + 64 * 65;
    float* Vs = Ks + 64 * 65;
    float* Ps = Vs + 64 * 65;

    const int qt  = blockIdx.x;    // 0..31
    const int h   = blockIdx.y;
    const int b   = blockIdx.z;
    const int tid = threadIdx.x;
    const int tx  = tid & 15;
    const int ty  = tid >> 4;
    const int q0  = qt * 64;

    const size_t head_base = (size_t)b * SEQ * DMODEL + (size_t)h * DHEAD;
    const float* Qg = g_Q + head_base;
    const float* Kg = g_K + head_base;
    const float* Vg = g_V + head_base;

    // Load Q tile (64 rows x 64 dims): 1024 float4 slots / 256 threads
    #pragma unroll
    for (int c = 0; c < 4; c++) {
        const int li = tid + c * 256;
        const int r  = li >> 4;
        const int d4 = (li & 15) * 4;
        float4 v = *(const float4*)(Qg + (size_t)(q0 + r) * DMODEL + d4);
        float* dst = Qs + r * 65 + d4;
        dst[0] = v.x; dst[1] = v.y; dst[2] = v.z; dst[3] = v.w;
    }

    float m_run[4], l_run[4], O[4][4];
    #pragma unroll
    for (int i = 0; i < 4; i++) {
        m_run[i] = -1e30f;
        l_run[i] = 0.0f;
        #pragma unroll
        for (int j = 0; j < 4; j++) O[i][j] = 0.0f;
    }

    for (int kt = 0; kt <= qt; kt++) {
        const int k0 = kt * 64;
        __syncthreads();   // prior iteration done reading Ks/Vs/Ps (also covers Q load on iter 0... load-sync below does)

        #pragma unroll
        for (int c = 0; c < 4; c++) {
            const int li = tid + c * 256;
            const int r  = li >> 4;
            const int d4 = (li & 15) * 4;
            float4 kv = *(const float4*)(Kg + (size_t)(k0 + r) * DMODEL + d4);
            float* kd = Ks + r * 65 + d4;
            kd[0] = kv.x; kd[1] = kv.y; kd[2] = kv.z; kd[3] = kv.w;
            float4 vv = *(const float4*)(Vg + (size_t)(k0 + r) * DMODEL + d4);
            float* vd = Vs + r * 65 + d4;
            vd[0] = vv.x; vd[1] = vv.y; vd[2] = vv.z; vd[3] = vv.w;
        }
        __syncthreads();

        // S = Q K^T (thread owns rows ty*4+i, cols tx*4+j)
        float s[4][4] = {};
        #pragma unroll 8
        for (int d = 0; d < 64; d++) {
            float rq[4], rk[4];
            #pragma unroll
            for (int i = 0; i < 4; i++) rq[i] = Qs[(ty * 4 + i) * 65 + d];
            #pragma unroll
            for (int j = 0; j < 4; j++) rk[j] = Ks[(tx * 4 + j) * 65 + d];
            #pragma unroll
            for (int i = 0; i < 4; i++)
                #pragma unroll
                for (int j = 0; j < 4; j++)
                    s[i][j] = fmaf(rq[i], rk[j], s[i][j]);
        }

        // Causal mask, only needed on diagonal tile. exp(-1e5 - m) == 0 in fp32,
        // so hard masking matches the reference's -1e5 fill exactly.
        if (kt == qt) {
            #pragma unroll
            for (int i = 0; i < 4; i++) {
                const int q = ty * 4 + i;
                #pragma unroll
                for (int j = 0; j < 4; j++)
                    if (tx * 4 + j > q) s[i][j] = -1e30f;
            }
        }

        // Online softmax (row reductions across the 16 threads sharing a row)
        #pragma unroll
        for (int i = 0; i < 4; i++) {
            float mx = fmaxf(fmaxf(s[i][0], s[i][1]), fmaxf(s[i][2], s[i][3]));
            #pragma unroll
            for (int off = 8; off >= 1; off >>= 1)
                mx = fmaxf(mx, __shfl_xor_sync(0xffffffffu, mx, off, 16));
            const float m_new = fmaxf(m_run[i], mx);
            const float alpha = __expf(m_run[i] - m_new);
            float rs = 0.0f;
            #pragma unroll
            for (int j = 0; j < 4; j++) {
                const float p = __expf(s[i][j] - m_new);
                s[i][j] = p;
                rs += p;
            }
            #pragma unroll
            for (int off = 8; off >= 1; off >>= 1)
                rs += __shfl_xor_sync(0xffffffffu, rs, off, 16);
            l_run[i] = l_run[i] * alpha + rs;
            m_run[i] = m_new;
            #pragma unroll
            for (int j = 0; j < 4; j++) O[i][j] *= alpha;
        }

        // P to smem, then O += P * V
        #pragma unroll
        for (int i = 0; i < 4; i++)
            #pragma unroll
            for (int j = 0; j < 4; j++)
                Ps[(ty * 4 + i) * 65 + tx * 4 + j] = s[i][j];
        __syncthreads();

        #pragma unroll 8
        for (int c = 0; c < 64; c++) {
            float rp[4], rv[4];
            #pragma unroll
            for (int i = 0; i < 4; i++) rp[i] = Ps[(ty * 4 + i) * 65 + c];
            #pragma unroll
            for (int j = 0; j < 4; j++) rv[j] = Vs[c * 65 + tx * 4 + j];
            #pragma unroll
            for (int i = 0; i < 4; i++)
                #pragma unroll
                for (int j = 0; j < 4; j++)
                    O[i][j] = fmaf(rp[i], rv[j], O[i][j]);
        }
    }

    // Epilogue: normalize and write Z[b, q, h, e]
    float* Zg = g_Z + head_base;
    #pragma unroll
    for (int i = 0; i < 4; i++) {
        const float inv = 1.0f / l_run[i];
        const int   q   = q0 + ty * 4 + i;
        #pragma unroll
        for (int j = 0; j < 4; j++)
            Zg[(size_t)q * DMODEL + tx * 4 + j] = O[i][j] * inv;
    }
}

// ---------------------------------------------------------------------------
// Kernel 3: output projection.
// W_O[h,e,d] flattens to contiguous row-major [1024,1024]: (h*64+e)*1024 + d.
// out[m,n] = sum_c Z[m,c]*Wo[c,n] + bO[n]
// grid = (16 n-tiles, 64 m-tiles), 256 threads
// ---------------------------------------------------------------------------
__global__ __launch_bounds__(256) void proj_kernel(
    const float* __restrict__ Wo, const float* __restrict__ bo,
    float* __restrict__ out)
{
    const int nt = blockIdx.x;
    const int mt = blockIdx.y;

    __shared__ float As[16][68];
    __shared__ float Bs[16][64];

    const int tid = threadIdx.x;
    const int tx  = tid & 15;
    const int ty  = tid >> 4;
    const int m0  = mt * 64;
    const int n0  = nt * 64;

    const int la_m  = tid >> 2;
    const int la_k4 = (tid & 3) * 4;
    const int lb_k  = tid >> 4;
    const int lb_n4 = (tid & 15) * 4;

    float acc[4][4] = {};

    for (int k0 = 0; k0 < DMODEL; k0 += 16) {
        float4 av = *(const float4*)(g_Z + (size_t)(m0 + la_m) * DMODEL + k0 + la_k4);
        As[la_k4 + 0][la_m] = av.x;
        As[la_k4 + 1][la_m] = av.y;
        As[la_k4 + 2][la_m] = av.z;
        As[la_k4 + 3][la_m] = av.w;
        *(float4*)&Bs[lb_k][lb_n4] =
            *(const float4*)(Wo + (size_t)(k0 + lb_k) * DMODEL + n0 + lb_n4);
        __syncthreads();

        #pragma unroll
        for (int kk = 0; kk < 16; kk++) {
            float ra[4], rb[4];
            #pragma unroll
            for (int i = 0; i < 4; i++) ra[i] = As[kk][ty * 4 + i];
            #pragma unroll
            for (int j = 0; j < 4; j++) rb[j] = Bs[kk][tx * 4 + j];
            #pragma unroll
            for (int i = 0; i < 4; i++)
                #pragma unroll
                for (int j = 0; j < 4; j++)
                    acc[i][j] = fmaf(ra[i], rb[j], acc[i][j]);
        }
        __syncthreads();
    }

    #pragma unroll
    for (int i = 0; i < 4; i++) {
        const int m = m0 + ty * 4 + i;
        #pragma unroll
        for (int j = 0; j < 4; j++) {
            const int n = n0 + tx * 4 + j;
            out[(size_t)m * DMODEL + n] = acc[i][j] + bo[n];
        }
    }
}

// ---------------------------------------------------------------------------
// Launch: QKV -> attention -> projection, all on the capture stream.
// ---------------------------------------------------------------------------
extern "C" void kernel_launch(void* const* d_in, const int* in_sizes, int n_in,
                              void* d_out, int out_size)
{
    (void)in_sizes; (void)n_in; (void)out_size;
    const float* x  = (const float*)d_in[0];
    const float* Wq = (const float*)d_in[1];
    const float* Wk = (const float*)d_in[2];
    const float* Wv = (const float*)d_in[3];
    const float* Wo = (const float*)d_in[4];
    const float* bq = (const float*)d_in[5];
    const float* bk = (const float*)d_in[6];
    const float* bv = (const float*)d_in[7];
    const float* bo = (const float*)d_in[8];
    float* out = (float*)d_out;

    qkv_kernel<<<dim3(16, 64, 3), 256>>>(x, Wq, Wk, Wv, bq, bk, bv);

    const int attn_smem = 4 * 64 * 65 * (int)sizeof(float);  // 66560 B
    cudaFuncSetAttribute(attn_kernel,
                         cudaFuncAttributeMaxDynamicSharedMemorySize, attn_smem);
    attn_kernel<<<dim3(SEQ / 64, NHEADS, BATCH), 256, attn_smem>>>();

    proj_kernel<<<dim3(16, 64), 256>>>(Wo, bo, out);
}

// round 5
// speedup vs baseline: 1.0018x; 1.0018x over previous
#include <cuda_runtime.h>
#include <math.h>

// Problem constants
#define BATCH  2
#define SEQ    2048
#define NHEADS 16
#define DMODEL 1024
#define DHEAD  64
#define MROWS  (BATCH*SEQ)   // 4096

// Scratch (allocation-free: __device__ globals). 4 x 16 MB.
__device__ float g_Q[(size_t)MROWS * DMODEL];
__device__ float g_K[(size_t)MROWS * DMODEL];
__device__ float g_V[(size_t)MROWS * DMODEL];
__device__ float g_Z[(size_t)MROWS * DMODEL];

// ---------------------------------------------------------------------------
// Kernel 1: fused QKV projection.
//   out[m, h*64+e] = (sum_k x[m,k] * W[h,k,e] + b[h,e]) * (scale if Q)
// Tile: BM=64, BN=64(=one head), BK=16. 256 threads, 4x4 micro-tile.
// grid = (16 n-tiles, 64 m-tiles, 3 matrices)
// ---------------------------------------------------------------------------
__global__ __launch_bounds__(256) void qkv_kernel(
    const float* __restrict__ x,
    const float* __restrict__ Wq, const float* __restrict__ Wk,
    const float* __restrict__ Wv,
    const float* __restrict__ bq, const float* __restrict__ bk,
    const float* __restrict__ bv)
{
    const int mat = blockIdx.z;              // 0=Q, 1=K, 2=V
    const int nt  = blockIdx.x;              // head index (BN=64=DHEAD)
    const int mt  = blockIdx.y;

    const float* W    = (mat == 0) ? Wq : (mat == 1) ? Wk : Wv;
    const float* bias = (mat == 0) ? bq : (mat == 1) ? bk : bv;
    float*       out  = (mat == 0) ? g_Q : (mat == 1) ? g_K : g_V;

    __shared__ float As[16][68];   // A transposed [k][m], pad to kill 4-way store conflicts
    __shared__ float Bs[16][64];   // [k][n]

    const int tid = threadIdx.x;
    const int tx  = tid & 15;
    const int ty  = tid >> 4;
    const int m0  = mt * 64;

    const float* Wh = W + (size_t)nt * (DMODEL * DHEAD);

    // loader indices
    const int la_m  = tid >> 2;            // 0..63
    const int la_k4 = (tid & 3) * 4;       // 0,4,8,12
    const int lb_k  = tid >> 4;            // 0..15
    const int lb_n4 = (tid & 15) * 4;      // 0..60

    float acc[4][4] = {};

    for (int k0 = 0; k0 < DMODEL; k0 += 16) {
        float4 av = *(const float4*)(x + (size_t)(m0 + la_m) * DMODEL + k0 + la_k4);
        As[la_k4 + 0][la_m] = av.x;
        As[la_k4 + 1][la_m] = av.y;
        As[la_k4 + 2][la_m] = av.z;
        As[la_k4 + 3][la_m] = av.w;
        *(float4*)&Bs[lb_k][lb_n4] =
            *(const float4*)(Wh + (size_t)(k0 + lb_k) * DHEAD + lb_n4);
        __syncthreads();

        #pragma unroll
        for (int kk = 0; kk < 16; kk++) {
            float ra[4], rb[4];
            #pragma unroll
            for (int i = 0; i < 4; i++) ra[i] = As[kk][ty * 4 + i];
            #pragma unroll
            for (int j = 0; j < 4; j++) rb[j] = Bs[kk][tx * 4 + j];
            #pragma unroll
            for (int i = 0; i < 4; i++)
                #pragma unroll
                for (int j = 0; j < 4; j++)
                    acc[i][j] = fmaf(ra[i], rb[j], acc[i][j]);
        }
        __syncthreads();
    }

    const float qscale = (mat == 0) ? 0.125f : 1.0f;   // 1/sqrt(64), applied to (xW+b)
    const int   n0     = nt * 64;
    #pragma unroll
    for (int i = 0; i < 4; i++) {
        const int m = m0 + ty * 4 + i;
        #pragma unroll
        for (int j = 0; j < 4; j++) {
            const int n = n0 + tx * 4 + j;
            out[(size_t)m * DMODEL + n] = (acc[i][j] + bias[n]) * qscale;
        }
    }
}

// ---------------------------------------------------------------------------
// Kernel 2: causal flash attention per (b, h, 64-query tile).
// Q pre-scaled. Online softmax, 4x4 register micro-tiles for both GEMMs.
// Dynamic smem: Qs/Ks/Vs/Ps each 64x65 floats = 66560 B.
// grid = (SEQ/64, NHEADS, BATCH), 256 threads
// ---------------------------------------------------------------------------
__global__ __launch_bounds__(256) void attn_kernel()
{
    extern __shared__ float sm[];
    float* Qs = sm;                // [64][65]
    float* Ks = Qs + 64 * 65;
    float* Vs = Ks + 64 * 65;
    float* Ps = Vs + 64 * 65;

    const int qt  = blockIdx.x;    // 0..31
    const int h   = blockIdx.y;
    const int b   = blockIdx.z;
    const int tid = threadIdx.x;
    const int tx  = tid & 15;
    const int ty  = tid >> 4;
    const int q0  = qt * 64;

    const size_t head_base = (size_t)b * SEQ * DMODEL + (size_t)h * DHEAD;
    const float* Qg = g_Q + head_base;
    const float* Kg = g_K + head_base;
    const float* Vg = g_V + head_base;

    // Load Q tile (64 rows x 64 dims): 1024 float4 slots / 256 threads
    #pragma unroll
    for (int c = 0; c < 4; c++) {
        const int li = tid + c * 256;
        const int r  = li >> 4;
        const int d4 = (li & 15) * 4;
        float4 v = *(const float4*)(Qg + (size_t)(q0 + r) * DMODEL + d4);
        float* dst = Qs + r * 65 + d4;
        dst[0] = v.x; dst[1] = v.y; dst[2] = v.z; dst[3] = v.w;
    }

    float m_run[4], l_run[4], O[4][4];
    #pragma unroll
    for (int i = 0; i < 4; i++) {
        m_run[i] = -1e30f;
        l_run[i] = 0.0f;
        #pragma unroll
        for (int j = 0; j < 4; j++) O[i][j] = 0.0f;
    }

    for (int kt = 0; kt <= qt; kt++) {
        const int k0 = kt * 64;
        __syncthreads();   // prior iteration done reading Ks/Vs/Ps (also covers Q load on iter 0... load-sync below does)

        #pragma unroll
        for (int c = 0; c < 4; c++) {
            const int li = tid + c * 256;
            const int r  = li >> 4;
            const int d4 = (li & 15) * 4;
            float4 kv = *(const float4*)(Kg + (size_t)(k0 + r) * DMODEL + d4);
            float* kd = Ks + r * 65 + d4;
            kd[0] = kv.x; kd[1] = kv.y; kd[2] = kv.z; kd[3] = kv.w;
            float4 vv = *(const float4*)(Vg + (size_t)(k0 + r) * DMODEL + d4);
            float* vd = Vs + r * 65 + d4;
            vd[0] = vv.x; vd[1] = vv.y; vd[2] = vv.z; vd[3] = vv.w;
        }
        __syncthreads();

        // S = Q K^T (thread owns rows ty*4+i, cols tx*4+j)
        float s[4][4] = {};
        #pragma unroll 8
        for (int d = 0; d < 64; d++) {
            float rq[4], rk[4];
            #pragma unroll
            for (int i = 0; i < 4; i++) rq[i] = Qs[(ty * 4 + i) * 65 + d];
            #pragma unroll
            for (int j = 0; j < 4; j++) rk[j] = Ks[(tx * 4 + j) * 65 + d];
            #pragma unroll
            for (int i = 0; i < 4; i++)
                #pragma unroll
                for (int j = 0; j < 4; j++)
                    s[i][j] = fmaf(rq[i], rk[j], s[i][j]);
        }

        // Causal mask, only needed on diagonal tile. exp(-1e5 - m) == 0 in fp32,
        // so hard masking matches the reference's -1e5 fill exactly.
        if (kt == qt) {
            #pragma unroll
            for (int i = 0; i < 4; i++) {
                const int q = ty * 4 + i;
                #pragma unroll
                for (int j = 0; j < 4; j++)
                    if (tx * 4 + j > q) s[i][j] = -1e30f;
            }
        }

        // Online softmax (row reductions across the 16 threads sharing a row)
        #pragma unroll
        for (int i = 0; i < 4; i++) {
            float mx = fmaxf(fmaxf(s[i][0], s[i][1]), fmaxf(s[i][2], s[i][3]));
            #pragma unroll
            for (int off = 8; off >= 1; off >>= 1)
                mx = fmaxf(mx, __shfl_xor_sync(0xffffffffu, mx, off, 16));
            const float m_new = fmaxf(m_run[i], mx);
            const float alpha = __expf(m_run[i] - m_new);
            float rs = 0.0f;
            #pragma unroll
            for (int j = 0; j < 4; j++) {
                const float p = __expf(s[i][j] - m_new);
                s[i][j] = p;
                rs += p;
            }
            #pragma unroll
            for (int off = 8; off >= 1; off >>= 1)
                rs += __shfl_xor_sync(0xffffffffu, rs, off, 16);
            l_run[i] = l_run[i] * alpha + rs;
            m_run[i] = m_new;
            #pragma unroll
            for (int j = 0; j < 4; j++) O[i][j] *= alpha;
        }

        // P to smem, then O += P * V
        #pragma unroll
        for (int i = 0; i < 4; i++)
            #pragma unroll
            for (int j = 0; j < 4; j++)
                Ps[(ty * 4 + i) * 65 + tx * 4 + j] = s[i][j];
        __syncthreads();

        #pragma unroll 8
        for (int c = 0; c < 64; c++) {
            float rp[4], rv[4];
            #pragma unroll
            for (int i = 0; i < 4; i++) rp[i] = Ps[(ty * 4 + i) * 65 + c];
            #pragma unroll
            for (int j = 0; j < 4; j++) rv[j] = Vs[c * 65 + tx * 4 + j];
            #pragma unroll
            for (int i = 0; i < 4; i++)
                #pragma unroll
                for (int j = 0; j < 4; j++)
                    O[i][j] = fmaf(rp[i], rv[j], O[i][j]);
        }
    }

    // Epilogue: normalize and write Z[b, q, h, e]
    float* Zg = g_Z + head_base;
    #pragma unroll
    for (int i = 0; i < 4; i++) {
        const float inv = 1.0f / l_run[i];
        const int   q   = q0 + ty * 4 + i;
        #pragma unroll
        for (int j = 0; j < 4; j++)
            Zg[(size_t)q * DMODEL + tx * 4 + j] = O[i][j] * inv;
    }
}

// ---------------------------------------------------------------------------
// Kernel 3: output projection.
// W_O[h,e,d] flattens to contiguous row-major [1024,1024]: (h*64+e)*1024 + d.
// out[m,n] = sum_c Z[m,c]*Wo[c,n] + bO[n]
// grid = (16 n-tiles, 64 m-tiles), 256 threads
// ---------------------------------------------------------------------------
__global__ __launch_bounds__(256) void proj_kernel(
    const float* __restrict__ Wo, const float* __restrict__ bo,
    float* __restrict__ out)
{
    const int nt = blockIdx.x;
    const int mt = blockIdx.y;

    __shared__ float As[16][68];
    __shared__ float Bs[16][64];

    const int tid = threadIdx.x;
    const int tx  = tid & 15;
    const int ty  = tid >> 4;
    const int m0  = mt * 64;
    const int n0  = nt * 64;

    const int la_m  = tid >> 2;
    const int la_k4 = (tid & 3) * 4;
    const int lb_k  = tid >> 4;
    const int lb_n4 = (tid & 15) * 4;

    float acc[4][4] = {};

    for (int k0 = 0; k0 < DMODEL; k0 += 16) {
        float4 av = *(const float4*)(g_Z + (size_t)(m0 + la_m) * DMODEL + k0 + la_k4);
        As[la_k4 + 0][la_m] = av.x;
        As[la_k4 + 1][la_m] = av.y;
        As[la_k4 + 2][la_m] = av.z;
        As[la_k4 + 3][la_m] = av.w;
        *(float4*)&Bs[lb_k][lb_n4] =
            *(const float4*)(Wo + (size_t)(k0 + lb_k) * DMODEL + n0 + lb_n4);
        __syncthreads();

        #pragma unroll
        for (int kk = 0; kk < 16; kk++) {
            float ra[4], rb[4];
            #pragma unroll
            for (int i = 0; i < 4; i++) ra[i] = As[kk][ty * 4 + i];
            #pragma unroll
            for (int j = 0; j < 4; j++) rb[j] = Bs[kk][tx * 4 + j];
            #pragma unroll
            for (int i = 0; i < 4; i++)
                #pragma unroll
                for (int j = 0; j < 4; j++)
                    acc[i][j] = fmaf(ra[i], rb[j], acc[i][j]);
        }
        __syncthreads();
    }

    #pragma unroll
    for (int i = 0; i < 4; i++) {
        const int m = m0 + ty * 4 + i;
        #pragma unroll
        for (int j = 0; j < 4; j++) {
            const int n = n0 + tx * 4 + j;
            out[(size_t)m * DMODEL + n] = acc[i][j] + bo[n];
        }
    }
}

// ---------------------------------------------------------------------------
// Launch: QKV -> attention -> projection, all on the capture stream.
// ---------------------------------------------------------------------------
extern "C" void kernel_launch(void* const* d_in, const int* in_sizes, int n_in,
                              void* d_out, int out_size)
{
    (void)in_sizes; (void)n_in; (void)out_size;
    const float* x  = (const float*)d_in[0];
    const float* Wq = (const float*)d_in[1];
    const float* Wk = (const float*)d_in[2];
    const float* Wv = (const float*)d_in[3];
    const float* Wo = (const float*)d_in[4];
    const float* bq = (const float*)d_in[5];
    const float* bk = (const float*)d_in[6];
    const float* bv = (const float*)d_in[7];
    const float* bo = (const float*)d_in[8];
    float* out = (float*)d_out;

    qkv_kernel<<<dim3(16, 64, 3), 256>>>(x, Wq, Wk, Wv, bq, bk, bv);

    const int attn_smem = 4 * 64 * 65 * (int)sizeof(float);  // 66560 B
    cudaFuncSetAttribute(attn_kernel,
                         cudaFuncAttributeMaxDynamicSharedMemorySize, attn_smem);
    attn_kernel<<<dim3(SEQ / 64, NHEADS, BATCH), 256, attn_smem>>>();

    proj_kernel<<<dim3(16, 64), 256>>>(Wo, bo, out);
}

// round 10
// speedup vs baseline: 1.0616x; 1.0597x over previous
#include <cuda_runtime.h>
#include <cuda_bf16.h>
#include <stdint.h>
#include <math.h>

#define BATCH  2
#define SEQ    2048
#define NHEADS 16
#define DMODEL 1024
#define DHEAD  64
#define MROWS  (BATCH*SEQ)   // 4096

// ------------------------------ scratch ------------------------------------
__device__ __align__(16) __nv_bfloat16 g_xh[(size_t)MROWS * DMODEL];
__device__ __align__(16) __nv_bfloat16 g_xl[(size_t)MROWS * DMODEL];
__device__ __align__(16) __nv_bfloat16 g_Wh[(size_t)DMODEL * DMODEL]; // Q weights [1024 n][1024 k]
__device__ __align__(16) __nv_bfloat16 g_Wl[(size_t)DMODEL * DMODEL];
__device__ __align__(16) float g_Q[(size_t)MROWS * DMODEL];
__device__ __align__(16) float g_K[(size_t)MROWS * DMODEL];
__device__ __align__(16) float g_V[(size_t)MROWS * DMODEL];
__device__ __align__(16) float g_Z[(size_t)MROWS * DMODEL];

// ------------------------------ helpers ------------------------------------
__device__ __forceinline__ void mma_bf16(float c[4], const uint32_t a[4],
                                         uint32_t b0, uint32_t b1) {
    asm volatile(
        "mma.sync.aligned.m16n8k16.row.col.f32.bf16.bf16.f32 "
        "{%0,%1,%2,%3}, {%4,%5,%6,%7}, {%8,%9}, {%0,%1,%2,%3};"
        : "+f"(c[0]), "+f"(c[1]), "+f"(c[2]), "+f"(c[3])
        : "r"(a[0]), "r"(a[1]), "r"(a[2]), "r"(a[3]), "r"(b0), "r"(b1));
}
__device__ __forceinline__ void bf16_split(float v, __nv_bfloat16& hi, __nv_bfloat16& lo) {
    hi = __float2bfloat16(v);
    lo = __float2bfloat16(v - __bfloat162float(hi));
}

// ------------------------- prep kernels (Q path only) -----------------------
__global__ __launch_bounds__(256) void convert_x_kernel(const float* __restrict__ x)
{
    int i = blockIdx.x * 256 + threadIdx.x;   // over MROWS*DMODEL/2
    float2 v = ((const float2*)x)[i];
    __nv_bfloat162 h, l;
    bf16_split(v.x, h.x, l.x);
    bf16_split(v.y, h.y, l.y);
    ((__nv_bfloat162*)g_xh)[i] = h;
    ((__nv_bfloat162*)g_xl)[i] = l;
}

// W_Q[h][k][e] -> g_Wh/g_Wl[(h*64 + e)][k]   (grid z = head)
__global__ __launch_bounds__(256) void transpose_wq(const float* __restrict__ Wq)
{
    const int h = blockIdx.z;
    const float* W = Wq + (size_t)h * DMODEL * DHEAD;
    __shared__ float t[32][33];
    const int k0 = blockIdx.x * 32, e0 = blockIdx.y * 32;
    const int tx = threadIdx.x & 31, ty = threadIdx.x >> 5;
    #pragma unroll
    for (int r = 0; r < 32; r += 8)
        t[ty + r][tx] = W[(size_t)(k0 + ty + r) * DHEAD + e0 + tx];
    __syncthreads();
    const int nbase = h * 64 + e0;
    #pragma unroll
    for (int r = 0; r < 32; r += 8) {
        float v = t[tx][ty + r];
        __nv_bfloat16 hi, lo; bf16_split(v, hi, lo);
        size_t idx = (size_t)(nbase + ty + r) * DMODEL + k0 + tx;
        g_Wh[idx] = hi; g_Wl[idx] = lo;
    }
}

// ------------------- mma.sync bf16 GEMM: Q = x @ Wq + bq, scaled ------------
// D[128,128] = sum over 3 bf16 plane-pairs of A[m][k]*B[n][k]^T, K=1024 each.
#define ASTR 40   // bf16 elements per smem row (20 words: conflict-free lanes)

__global__ __launch_bounds__(256) void gemm_q_kernel(const float* __restrict__ bq)
{
    __shared__ __align__(16) __nv_bfloat16 As[128 * ASTR];
    __shared__ __align__(16) __nv_bfloat16 Bs[128 * ASTR];

    const int tid = threadIdx.x, wid = tid >> 5, lane = tid & 31;
    const int m0 = blockIdx.y * 128, n0 = blockIdx.x * 128;
    const int wm = (wid & 3) * 32, wn = (wid >> 2) * 64;
    const int g  = lane >> 2;            // fragment row group
    const int kq = (lane & 3) * 2;       // fragment k-pair offset

    const __nv_bfloat16* Ap[3] = {g_xh, g_xl, g_xh};
    const __nv_bfloat16* Bp[3] = {g_Wh, g_Wh, g_Wl};
    const int NC = 96;                   // 3 planes x 32 chunks of K=32

    const int lr0 = tid >> 2, lseg = (tid & 3) * 8;   // loader row, k offset

    uint4 av[2], bv[2];
    auto load_regs = [&](int c) {
        const int p = c >> 5, k0 = (c & 31) * 32;
        #pragma unroll
        for (int it = 0; it < 2; it++) {
            const int r = lr0 + it * 64;
            av[it] = *(const uint4*)(Ap[p] + (size_t)(m0 + r) * DMODEL + k0 + lseg);
            bv[it] = *(const uint4*)(Bp[p] + (size_t)(n0 + r) * DMODEL + k0 + lseg);
        }
    };
    auto store_smem = [&]() {
        #pragma unroll
        for (int it = 0; it < 2; it++) {
            const int r = lr0 + it * 64;
            *(uint4*)&As[r * ASTR + lseg] = av[it];
            *(uint4*)&Bs[r * ASTR + lseg] = bv[it];
        }
    };

    float C[2][8][4];
    #pragma unroll
    for (int i = 0; i < 2; i++)
        #pragma unroll
        for (int j = 0; j < 8; j++)
            #pragma unroll
            for (int q = 0; q < 4; q++) C[i][j][q] = 0.0f;

    load_regs(0);
    store_smem();
    __syncthreads();

    for (int c = 0; c < NC; c++) {
        if (c + 1 < NC) load_regs(c + 1);

        #pragma unroll
        for (int ks = 0; ks < 2; ks++) {
            const int kc = ks * 16 + kq;
            uint32_t ar[2][4];
            #pragma unroll
            for (int i = 0; i < 2; i++) {
                const int row = wm + i * 16 + g;
                ar[i][0] = *(const uint32_t*)&As[(row)     * ASTR + kc];
                ar[i][1] = *(const uint32_t*)&As[(row + 8) * ASTR + kc];
                ar[i][2] = *(const uint32_t*)&As[(row)     * ASTR + kc + 8];
                ar[i][3] = *(const uint32_t*)&As[(row + 8) * ASTR + kc + 8];
            }
            #pragma unroll
            for (int j = 0; j < 8; j++) {
                const int nrow = wn + j * 8 + g;
                const uint32_t bb0 = *(const uint32_t*)&Bs[nrow * ASTR + kc];
                const uint32_t bb1 = *(const uint32_t*)&Bs[nrow * ASTR + kc + 8];
                mma_bf16(C[0][j], ar[0], bb0, bb1);
                mma_bf16(C[1][j], ar[1], bb0, bb1);
            }
        }
        __syncthreads();
        if (c + 1 < NC) {
            store_smem();
            __syncthreads();
        }
    }

    // epilogue: (acc + bq) * 1/sqrt(64)
    const int er = m0 + wm + g;
    const int ec = wn + kq;
    #pragma unroll
    for (int i = 0; i < 2; i++) {
        #pragma unroll
        for (int j = 0; j < 8; j++) {
            const int col = n0 + ec + j * 8;
            const float bx = bq[col], by = bq[col + 1];
            float2 v0 = make_float2((C[i][j][0] + bx) * 0.125f,
                                    (C[i][j][1] + by) * 0.125f);
            float2 v1 = make_float2((C[i][j][2] + bx) * 0.125f,
                                    (C[i][j][3] + by) * 0.125f);
            const int row = er + i * 16;
            *(float2*)&g_Q[(size_t)row * DMODEL + col]       = v0;
            *(float2*)&g_Q[(size_t)(row + 8) * DMODEL + col] = v1;
        }
    }
}

// ---------------- K/V projection: PROVEN R4 fp32 kernel (mat = z+1) ---------
__global__ __launch_bounds__(256) void kv_kernel(
    const float* __restrict__ x,
    const float* __restrict__ Wk, const float* __restrict__ Wv,
    const float* __restrict__ bk, const float* __restrict__ bv)
{
    const int mat = blockIdx.z;              // 0=K, 1=V
    const int nt  = blockIdx.x;              // head index
    const int mt  = blockIdx.y;

    const float* W    = (mat == 0) ? Wk : Wv;
    const float* bias = (mat == 0) ? bk : bv;
    float*       out  = (mat == 0) ? g_K : g_V;

    __shared__ float As[16][68];
    __shared__ float Bs[16][64];

    const int tid = threadIdx.x;
    const int tx  = tid & 15;
    const int ty  = tid >> 4;
    const int m0  = mt * 64;

    const float* Wh = W + (size_t)nt * (DMODEL * DHEAD);

    const int la_m  = tid >> 2;
    const int la_k4 = (tid & 3) * 4;
    const int lb_k  = tid >> 4;
    const int lb_n4 = (tid & 15) * 4;

    float acc[4][4] = {};

    for (int k0 = 0; k0 < DMODEL; k0 += 16) {
        float4 av = *(const float4*)(x + (size_t)(m0 + la_m) * DMODEL + k0 + la_k4);
        As[la_k4 + 0][la_m] = av.x;
        As[la_k4 + 1][la_m] = av.y;
        As[la_k4 + 2][la_m] = av.z;
        As[la_k4 + 3][la_m] = av.w;
        *(float4*)&Bs[lb_k][lb_n4] =
            *(const float4*)(Wh + (size_t)(k0 + lb_k) * DHEAD + lb_n4);
        __syncthreads();

        #pragma unroll
        for (int kk = 0; kk < 16; kk++) {
            float ra[4], rb[4];
            #pragma unroll
            for (int i = 0; i < 4; i++) ra[i] = As[kk][ty * 4 + i];
            #pragma unroll
            for (int j = 0; j < 4; j++) rb[j] = Bs[kk][tx * 4 + j];
            #pragma unroll
            for (int i = 0; i < 4; i++)
                #pragma unroll
                for (int j = 0; j < 4; j++)
                    acc[i][j] = fmaf(ra[i], rb[j], acc[i][j]);
        }
        __syncthreads();
    }

    const int n0 = nt * 64;
    #pragma unroll
    for (int i = 0; i < 4; i++) {
        const int m = m0 + ty * 4 + i;
        #pragma unroll
        for (int j = 0; j < 4; j++) {
            const int n = n0 + tx * 4 + j;
            out[(size_t)m * DMODEL + n] = acc[i][j] + bias[n];
        }
    }
}

// ------------------------- attention (PROVEN R4, fp32 Z) --------------------
__global__ __launch_bounds__(256) void attn_kernel()
{
    extern __shared__ float sm[];
    float* Qs = sm;                // [64][65]
    float* Ks = Qs + 64 * 65;
    float* Vs = Ks + 64 * 65;
    float* Ps = Vs + 64 * 65;

    const int qt  = blockIdx.x;
    const int h   = blockIdx.y;
    const int b   = blockIdx.z;
    const int tid = threadIdx.x;
    const int tx  = tid & 15;
    const int ty  = tid >> 4;
    const int q0  = qt * 64;

    const size_t head_base = (size_t)b * SEQ * DMODEL + (size_t)h * DHEAD;
    const float* Qg = g_Q + head_base;
    const float* Kg = g_K + head_base;
    const float* Vg = g_V + head_base;

    #pragma unroll
    for (int c = 0; c < 4; c++) {
        const int li = tid + c * 256;
        const int r  = li >> 4;
        const int d4 = (li & 15) * 4;
        float4 v = *(const float4*)(Qg + (size_t)(q0 + r) * DMODEL + d4);
        float* dq = Qs + r * 65 + d4;
        dq[0] = v.x; dq[1] = v.y; dq[2] = v.z; dq[3] = v.w;
    }

    float m_run[4], l_run[4], O[4][4];
    #pragma unroll
    for (int i = 0; i < 4; i++) {
        m_run[i] = -1e30f; l_run[i] = 0.0f;
        #pragma unroll
        for (int j = 0; j < 4; j++) O[i][j] = 0.0f;
    }

    for (int kt = 0; kt <= qt; kt++) {
        const int k0 = kt * 64;
        __syncthreads();
        #pragma unroll
        for (int c = 0; c < 4; c++) {
            const int li = tid + c * 256;
            const int r  = li >> 4;
            const int d4 = (li & 15) * 4;
            float4 kv = *(const float4*)(Kg + (size_t)(k0 + r) * DMODEL + d4);
            float* kd = Ks + r * 65 + d4;
            kd[0] = kv.x; kd[1] = kv.y; kd[2] = kv.z; kd[3] = kv.w;
            float4 vv = *(const float4*)(Vg + (size_t)(k0 + r) * DMODEL + d4);
            float* vd = Vs + r * 65 + d4;
            vd[0] = vv.x; vd[1] = vv.y; vd[2] = vv.z; vd[3] = vv.w;
        }
        __syncthreads();

        float s[4][4] = {};
        #pragma unroll 8
        for (int d = 0; d < 64; d++) {
            float rq[4], rk[4];
            #pragma unroll
            for (int i = 0; i < 4; i++) rq[i] = Qs[(ty * 4 + i) * 65 + d];
            #pragma unroll
            for (int j = 0; j < 4; j++) rk[j] = Ks[(tx * 4 + j) * 65 + d];
            #pragma unroll
            for (int i = 0; i < 4; i++)
                #pragma unroll
                for (int j = 0; j < 4; j++)
                    s[i][j] = fmaf(rq[i], rk[j], s[i][j]);
        }

        if (kt == qt) {
            #pragma unroll
            for (int i = 0; i < 4; i++) {
                const int q = ty * 4 + i;
                #pragma unroll
                for (int j = 0; j < 4; j++)
                    if (tx * 4 + j > q) s[i][j] = -1e30f;
            }
        }

        #pragma unroll
        for (int i = 0; i < 4; i++) {
            float mx = fmaxf(fmaxf(s[i][0], s[i][1]), fmaxf(s[i][2], s[i][3]));
            #pragma unroll
            for (int off = 8; off >= 1; off >>= 1)
                mx = fmaxf(mx, __shfl_xor_sync(0xffffffffu, mx, off, 16));
            const float m_new = fmaxf(m_run[i], mx);
            const float alpha = __expf(m_run[i] - m_new);
            float rs = 0.0f;
            #pragma unroll
            for (int j = 0; j < 4; j++) {
                const float p = __expf(s[i][j] - m_new);
                s[i][j] = p; rs += p;
            }
            #pragma unroll
            for (int off = 8; off >= 1; off >>= 1)
                rs += __shfl_xor_sync(0xffffffffu, rs, off, 16);
            l_run[i] = l_run[i] * alpha + rs;
            m_run[i] = m_new;
            #pragma unroll
            for (int j = 0; j < 4; j++) O[i][j] *= alpha;
        }

        #pragma unroll
        for (int i = 0; i < 4; i++)
            #pragma unroll
            for (int j = 0; j < 4; j++)
                Ps[(ty * 4 + i) * 65 + tx * 4 + j] = s[i][j];
        __syncthreads();

        #pragma unroll 8
        for (int c = 0; c < 64; c++) {
            float rp[4], rv[4];
            #pragma unroll
            for (int i = 0; i < 4; i++) rp[i] = Ps[(ty * 4 + i) * 65 + c];
            #pragma unroll
            for (int j = 0; j < 4; j++) rv[j] = Vs[c * 65 + tx * 4 + j];
            #pragma unroll
            for (int i = 0; i < 4; i++)
                #pragma unroll
                for (int j = 0; j < 4; j++)
                    O[i][j] = fmaf(rp[i], rv[j], O[i][j]);
        }
    }

    float* Zg = g_Z + head_base;
    #pragma unroll
    for (int i = 0; i < 4; i++) {
        const float inv = 1.0f / l_run[i];
        const int   q   = q0 + ty * 4 + i;
        #pragma unroll
        for (int j = 0; j < 4; j++)
            Zg[(size_t)q * DMODEL + tx * 4 + j] = O[i][j] * inv;
    }
}

// ------------------------- projection (PROVEN R4, fp32) ---------------------
__global__ __launch_bounds__(256) void proj_kernel(
    const float* __restrict__ Wo, const float* __restrict__ bo,
    float* __restrict__ out)
{
    const int nt = blockIdx.x;
    const int mt = blockIdx.y;

    __shared__ float As[16][68];
    __shared__ float Bs[16][64];

    const int tid = threadIdx.x;
    const int tx  = tid & 15;
    const int ty  = tid >> 4;
    const int m0  = mt * 64;
    const int n0  = nt * 64;

    const int la_m  = tid >> 2;
    const int la_k4 = (tid & 3) * 4;
    const int lb_k  = tid >> 4;
    const int lb_n4 = (tid & 15) * 4;

    float acc[4][4] = {};

    for (int k0 = 0; k0 < DMODEL; k0 += 16) {
        float4 av = *(const float4*)(g_Z + (size_t)(m0 + la_m) * DMODEL + k0 + la_k4);
        As[la_k4 + 0][la_m] = av.x;
        As[la_k4 + 1][la_m] = av.y;
        As[la_k4 + 2][la_m] = av.z;
        As[la_k4 + 3][la_m] = av.w;
        *(float4*)&Bs[lb_k][lb_n4] =
            *(const float4*)(Wo + (size_t)(k0 + lb_k) * DMODEL + n0 + lb_n4);
        __syncthreads();

        #pragma unroll
        for (int kk = 0; kk < 16; kk++) {
            float ra[4], rb[4];
            #pragma unroll
            for (int i = 0; i < 4; i++) ra[i] = As[kk][ty * 4 + i];
            #pragma unroll
            for (int j = 0; j < 4; j++) rb[j] = Bs[kk][tx * 4 + j];
            #pragma unroll
            for (int i = 0; i < 4; i++)
                #pragma unroll
                for (int j = 0; j < 4; j++)
                    acc[i][j] = fmaf(ra[i], rb[j], acc[i][j]);
        }
        __syncthreads();
    }

    #pragma unroll
    for (int i = 0; i < 4; i++) {
        const int m = m0 + ty * 4 + i;
        #pragma unroll
        for (int j = 0; j < 4; j++) {
            const int n = n0 + tx * 4 + j;
            out[(size_t)m * DMODEL + n] = acc[i][j] + bo[n];
        }
    }
}

// ------------------------------ launch --------------------------------------
extern "C" void kernel_launch(void* const* d_in, const int* in_sizes, int n_in,
                              void* d_out, int out_size)
{
    (void)in_sizes; (void)n_in; (void)out_size;
    const float* x  = (const float*)d_in[0];
    const float* Wq = (const float*)d_in[1];
    const float* Wk = (const float*)d_in[2];
    const float* Wv = (const float*)d_in[3];
    const float* Wo = (const float*)d_in[4];
    const float* bq = (const float*)d_in[5];
    const float* bk = (const float*)d_in[6];
    const float* bv = (const float*)d_in[7];
    const float* bo = (const float*)d_in[8];
    float* out = (float*)d_out;

    const int attn_smem = 4 * 64 * 65 * (int)sizeof(float);
    cudaFuncSetAttribute(attn_kernel,
                         cudaFuncAttributeMaxDynamicSharedMemorySize, attn_smem);

    // Q path (experimental mma.sync bf16-split)
    convert_x_kernel<<<(MROWS * DMODEL / 2) / 256, 256>>>(x);
    transpose_wq<<<dim3(32, 2, 16), 256>>>(Wq);
    gemm_q_kernel<<<dim3(8, 32), 256>>>(bq);

    // K/V path (proven fp32)
    kv_kernel<<<dim3(16, 64, 2), 256>>>(x, Wk, Wv, bk, bv);

    attn_kernel<<<dim3(SEQ / 64, NHEADS, BATCH), 256, attn_smem>>>();

    proj_kernel<<<dim3(16, 64), 256>>>(Wo, bo, out);
}

// round 11
// speedup vs baseline: 1.2443x; 1.1721x over previous
#include <cuda_runtime.h>
#include <cuda_bf16.h>
#include <stdint.h>
#include <math.h>

#define BATCH  2
#define SEQ    2048
#define NHEADS 16
#define DMODEL 1024
#define DHEAD  64
#define MROWS  (BATCH*SEQ)   // 4096

// ------------------------------ scratch ------------------------------------
// NOTE: only ever referenced from DEVICE code (host-side references to
// __device__ symbols yield garbage addresses — R8/R9 root cause).
__device__ __align__(16) __nv_bfloat16 g_xh[(size_t)MROWS * DMODEL];
__device__ __align__(16) __nv_bfloat16 g_xl[(size_t)MROWS * DMODEL];
__device__ __align__(16) __nv_bfloat16 g_Wh[(size_t)3 * DMODEL * DMODEL]; // [3072 n][1024 k]
__device__ __align__(16) __nv_bfloat16 g_Wl[(size_t)3 * DMODEL * DMODEL];
__device__ __align__(16) __nv_bfloat16 g_Woh[(size_t)DMODEL * DMODEL];    // [1024 d][1024 c]
__device__ __align__(16) __nv_bfloat16 g_Wol[(size_t)DMODEL * DMODEL];
__device__ __align__(16) float g_Q[(size_t)MROWS * DMODEL];
__device__ __align__(16) float g_K[(size_t)MROWS * DMODEL];
__device__ __align__(16) float g_V[(size_t)MROWS * DMODEL];
__device__ __align__(16) __nv_bfloat16 g_Zh[(size_t)MROWS * DMODEL];
__device__ __align__(16) __nv_bfloat16 g_Zl[(size_t)MROWS * DMODEL];

// ------------------------------ helpers ------------------------------------
__device__ __forceinline__ void mma_bf16(float c[4], const uint32_t a[4],
                                         uint32_t b0, uint32_t b1) {
    asm volatile(
        "mma.sync.aligned.m16n8k16.row.col.f32.bf16.bf16.f32 "
        "{%0,%1,%2,%3}, {%4,%5,%6,%7}, {%8,%9}, {%0,%1,%2,%3};"
        : "+f"(c[0]), "+f"(c[1]), "+f"(c[2]), "+f"(c[3])
        : "r"(a[0]), "r"(a[1]), "r"(a[2]), "r"(a[3]), "r"(b0), "r"(b1));
}
__device__ __forceinline__ void bf16_split(float v, __nv_bfloat16& hi, __nv_bfloat16& lo) {
    hi = __float2bfloat16(v);
    lo = __float2bfloat16(v - __bfloat162float(hi));
}

// ------------------------- prep kernels -------------------------------------
__global__ __launch_bounds__(256) void convert_x_kernel(const float* __restrict__ x)
{
    int i = blockIdx.x * 256 + threadIdx.x;   // over MROWS*DMODEL/2
    float2 v = ((const float2*)x)[i];
    __nv_bfloat162 h, l;
    bf16_split(v.x, h.x, l.x);
    bf16_split(v.y, h.y, l.y);
    ((__nv_bfloat162*)g_xh)[i] = h;
    ((__nv_bfloat162*)g_xl)[i] = l;
}

// W_{Q,K,V}[h][k][e] -> g_Wh/g_Wl[(mat*1024 + h*64 + e)][k]  (z = mat*16+h)
__global__ __launch_bounds__(256) void transpose_wqkv(
    const float* __restrict__ Wq, const float* __restrict__ Wk,
    const float* __restrict__ Wv)
{
    const int z = blockIdx.z, mat = z >> 4, h = z & 15;
    const float* W = ((mat == 0) ? Wq : (mat == 1) ? Wk : Wv) + (size_t)h * DMODEL * DHEAD;
    __shared__ float t[32][33];
    const int k0 = blockIdx.x * 32, e0 = blockIdx.y * 32;
    const int tx = threadIdx.x & 31, ty = threadIdx.x >> 5;
    #pragma unroll
    for (int r = 0; r < 32; r += 8)
        t[ty + r][tx] = W[(size_t)(k0 + ty + r) * DHEAD + e0 + tx];
    __syncthreads();
    const int nbase = mat * 1024 + h * 64 + e0;
    #pragma unroll
    for (int r = 0; r < 32; r += 8) {
        float v = t[tx][ty + r];
        __nv_bfloat16 hi, lo; bf16_split(v, hi, lo);
        size_t idx = (size_t)(nbase + ty + r) * DMODEL + k0 + tx;
        g_Wh[idx] = hi; g_Wl[idx] = lo;
    }
}

// W_O flat [1024 c][1024 d] -> g_Woh/g_Wol[d][c]
__global__ __launch_bounds__(256) void transpose_wo(const float* __restrict__ Wo)
{
    __shared__ float t[32][33];
    const int d0 = blockIdx.x * 32, c0 = blockIdx.y * 32;
    const int tx = threadIdx.x & 31, ty = threadIdx.x >> 5;
    #pragma unroll
    for (int r = 0; r < 32; r += 8)
        t[ty + r][tx] = Wo[(size_t)(c0 + ty + r) * DMODEL + d0 + tx];
    __syncthreads();
    #pragma unroll
    for (int r = 0; r < 32; r += 8) {
        float v = t[tx][ty + r];
        __nv_bfloat16 hi, lo; bf16_split(v, hi, lo);
        size_t idx = (size_t)(d0 + ty + r) * DMODEL + c0 + tx;
        g_Woh[idx] = hi; g_Wol[idx] = lo;
    }
}

// ------------------- mma.sync bf16-split GEMM (proven R10 body) -------------
// D[128,128] = sum over 3 plane-pairs of A[m][k]*B[n][k]^T, K=1024 each.
// mode 0: QKV  (A = x-split,  B = g_Wh/g_Wl [3072][1024], out g_Q/g_K/g_V)
// mode 1: proj (A = Z-split,  B = g_Woh/g_Wol,            out = outp + b_O)
#define ASTR 40   // bf16 elements per smem row (20 words: conflict-free lanes)

__global__ __launch_bounds__(256) void gemm_kernel(
    const float* __restrict__ b0, const float* __restrict__ b1,
    const float* __restrict__ b2, float* __restrict__ outp, int mode)
{
    __shared__ __align__(16) __nv_bfloat16 As[128 * ASTR];
    __shared__ __align__(16) __nv_bfloat16 Bs[128 * ASTR];

    const int tid = threadIdx.x, wid = tid >> 5, lane = tid & 31;
    const int m0 = blockIdx.y * 128, n0 = blockIdx.x * 128;
    const int wm = (wid & 3) * 32, wn = (wid >> 2) * 64;
    const int g  = lane >> 2;            // fragment row group
    const int kq = (lane & 3) * 2;       // fragment k-pair offset

    // Resolve scratch pointers in DEVICE code.
    const __nv_bfloat16 *ah, *al, *bh, *bl;
    if (mode == 0) { ah = g_xh; al = g_xl; bh = g_Wh;  bl = g_Wl;  }
    else           { ah = g_Zh; al = g_Zl; bh = g_Woh; bl = g_Wol; }
    const __nv_bfloat16* Ap[3] = {ah, al, ah};
    const __nv_bfloat16* Bp[3] = {bh, bh, bl};
    const int NC = 96;                   // 3 planes x 32 chunks of K=32

    const int lr0 = tid >> 2, lseg = (tid & 3) * 8;   // loader row, k offset

    uint4 av[2], bv[2];
    auto load_regs = [&](int c) {
        const int p = c >> 5, k0 = (c & 31) * 32;
        #pragma unroll
        for (int it = 0; it < 2; it++) {
            const int r = lr0 + it * 64;
            av[it] = *(const uint4*)(Ap[p] + (size_t)(m0 + r) * DMODEL + k0 + lseg);
            bv[it] = *(const uint4*)(Bp[p] + (size_t)(n0 + r) * DMODEL + k0 + lseg);
        }
    };
    auto store_smem = [&]() {
        #pragma unroll
        for (int it = 0; it < 2; it++) {
            const int r = lr0 + it * 64;
            *(uint4*)&As[r * ASTR + lseg] = av[it];
            *(uint4*)&Bs[r * ASTR + lseg] = bv[it];
        }
    };

    float C[2][8][4];
    #pragma unroll
    for (int i = 0; i < 2; i++)
        #pragma unroll
        for (int j = 0; j < 8; j++)
            #pragma unroll
            for (int q = 0; q < 4; q++) C[i][j][q] = 0.0f;

    load_regs(0);
    store_smem();
    __syncthreads();

    for (int c = 0; c < NC; c++) {
        if (c + 1 < NC) load_regs(c + 1);

        #pragma unroll
        for (int ks = 0; ks < 2; ks++) {
            const int kc = ks * 16 + kq;
            uint32_t ar[2][4];
            #pragma unroll
            for (int i = 0; i < 2; i++) {
                const int row = wm + i * 16 + g;
                ar[i][0] = *(const uint32_t*)&As[(row)     * ASTR + kc];
                ar[i][1] = *(const uint32_t*)&As[(row + 8) * ASTR + kc];
                ar[i][2] = *(const uint32_t*)&As[(row)     * ASTR + kc + 8];
                ar[i][3] = *(const uint32_t*)&As[(row + 8) * ASTR + kc + 8];
            }
            #pragma unroll
            for (int j = 0; j < 8; j++) {
                const int nrow = wn + j * 8 + g;
                const uint32_t bb0 = *(const uint32_t*)&Bs[nrow * ASTR + kc];
                const uint32_t bb1 = *(const uint32_t*)&Bs[nrow * ASTR + kc + 8];
                mma_bf16(C[0][j], ar[0], bb0, bb1);
                mma_bf16(C[1][j], ar[1], bb0, bb1);
            }
        }
        __syncthreads();
        if (c + 1 < NC) {
            store_smem();
            __syncthreads();
        }
    }

    // ----- epilogue: bias + optional Q scale -----
    const int mat  = n0 >> 10;                 // 0 for mode 1
    const int col0 = n0 & 1023;
    const float scale = (mode == 0 && mat == 0) ? 0.125f : 1.0f;
    const float* bias = (mode == 1) ? b0 : ((mat == 0) ? b0 : (mat == 1) ? b1 : b2);
    float* dst = (mode == 1) ? outp : ((mat == 0) ? g_Q : (mat == 1) ? g_K : g_V);

    const int er = m0 + wm + g;
    const int ec = wn + kq;
    #pragma unroll
    for (int i = 0; i < 2; i++) {
        #pragma unroll
        for (int j = 0; j < 8; j++) {
            const int col = col0 + ec + j * 8;
            const float bx = bias[col], by = bias[col + 1];
            float2 v0 = make_float2((C[i][j][0] + bx) * scale,
                                    (C[i][j][1] + by) * scale);
            float2 v1 = make_float2((C[i][j][2] + bx) * scale,
                                    (C[i][j][3] + by) * scale);
            const int row = er + i * 16;
            *(float2*)&dst[(size_t)row * DMODEL + col]       = v0;
            *(float2*)&dst[(size_t)(row + 8) * DMODEL + col] = v1;
        }
    }
}

// ------------------------- attention (proven SIMT) --------------------------
__global__ __launch_bounds__(256) void attn_kernel()
{
    extern __shared__ float sm[];
    float* Qs = sm;                // [64][65]
    float* Ks = Qs + 64 * 65;
    float* Vs = Ks + 64 * 65;
    float* Ps = Vs + 64 * 65;

    const int qt  = blockIdx.x;
    const int h   = blockIdx.y;
    const int b   = blockIdx.z;
    const int tid = threadIdx.x;
    const int tx  = tid & 15;
    const int ty  = tid >> 4;
    const int q0  = qt * 64;

    const size_t head_base = (size_t)b * SEQ * DMODEL + (size_t)h * DHEAD;
    const float* Qg = g_Q + head_base;
    const float* Kg = g_K + head_base;
    const float* Vg = g_V + head_base;

    #pragma unroll
    for (int c = 0; c < 4; c++) {
        const int li = tid + c * 256;
        const int r  = li >> 4;
        const int d4 = (li & 15) * 4;
        float4 v = *(const float4*)(Qg + (size_t)(q0 + r) * DMODEL + d4);
        float* dq = Qs + r * 65 + d4;
        dq[0] = v.x; dq[1] = v.y; dq[2] = v.z; dq[3] = v.w;
    }

    float m_run[4], l_run[4], O[4][4];
    #pragma unroll
    for (int i = 0; i < 4; i++) {
        m_run[i] = -1e30f; l_run[i] = 0.0f;
        #pragma unroll
        for (int j = 0; j < 4; j++) O[i][j] = 0.0f;
    }

    for (int kt = 0; kt <= qt; kt++) {
        const int k0 = kt * 64;
        __syncthreads();
        #pragma unroll
        for (int c = 0; c < 4; c++) {
            const int li = tid + c * 256;
            const int r  = li >> 4;
            const int d4 = (li & 15) * 4;
            float4 kv = *(const float4*)(Kg + (size_t)(k0 + r) * DMODEL + d4);
            float* kd = Ks + r * 65 + d4;
            kd[0] = kv.x; kd[1] = kv.y; kd[2] = kv.z; kd[3] = kv.w;
            float4 vv = *(const float4*)(Vg + (size_t)(k0 + r) * DMODEL + d4);
            float* vd = Vs + r * 65 + d4;
            vd[0] = vv.x; vd[1] = vv.y; vd[2] = vv.z; vd[3] = vv.w;
        }
        __syncthreads();

        float s[4][4] = {};
        #pragma unroll 8
        for (int d = 0; d < 64; d++) {
            float rq[4], rk[4];
            #pragma unroll
            for (int i = 0; i < 4; i++) rq[i] = Qs[(ty * 4 + i) * 65 + d];
            #pragma unroll
            for (int j = 0; j < 4; j++) rk[j] = Ks[(tx * 4 + j) * 65 + d];
            #pragma unroll
            for (int i = 0; i < 4; i++)
                #pragma unroll
                for (int j = 0; j < 4; j++)
                    s[i][j] = fmaf(rq[i], rk[j], s[i][j]);
        }

        if (kt == qt) {
            #pragma unroll
            for (int i = 0; i < 4; i++) {
                const int q = ty * 4 + i;
                #pragma unroll
                for (int j = 0; j < 4; j++)
                    if (tx * 4 + j > q) s[i][j] = -1e30f;
            }
        }

        #pragma unroll
        for (int i = 0; i < 4; i++) {
            float mx = fmaxf(fmaxf(s[i][0], s[i][1]), fmaxf(s[i][2], s[i][3]));
            #pragma unroll
            for (int off = 8; off >= 1; off >>= 1)
                mx = fmaxf(mx, __shfl_xor_sync(0xffffffffu, mx, off, 16));
            const float m_new = fmaxf(m_run[i], mx);
            const float alpha = __expf(m_run[i] - m_new);
            float rs = 0.0f;
            #pragma unroll
            for (int j = 0; j < 4; j++) {
                const float p = __expf(s[i][j] - m_new);
                s[i][j] = p; rs += p;
            }
            #pragma unroll
            for (int off = 8; off >= 1; off >>= 1)
                rs += __shfl_xor_sync(0xffffffffu, rs, off, 16);
            l_run[i] = l_run[i] * alpha + rs;
            m_run[i] = m_new;
            #pragma unroll
            for (int j = 0; j < 4; j++) O[i][j] *= alpha;
        }

        #pragma unroll
        for (int i = 0; i < 4; i++)
            #pragma unroll
            for (int j = 0; j < 4; j++)
                Ps[(ty * 4 + i) * 65 + tx * 4 + j] = s[i][j];
        __syncthreads();

        #pragma unroll 8
        for (int c = 0; c < 64; c++) {
            float rp[4], rv[4];
            #pragma unroll
            for (int i = 0; i < 4; i++) rp[i] = Ps[(ty * 4 + i) * 65 + c];
            #pragma unroll
            for (int j = 0; j < 4; j++) rv[j] = Vs[c * 65 + tx * 4 + j];
            #pragma unroll
            for (int i = 0; i < 4; i++)
                #pragma unroll
                for (int j = 0; j < 4; j++)
                    O[i][j] = fmaf(rp[i], rv[j], O[i][j]);
        }
    }

    // epilogue: normalize + split-bf16 Z for the proj GEMM
    #pragma unroll
    for (int i = 0; i < 4; i++) {
        const float inv = 1.0f / l_run[i];
        const int   q   = q0 + ty * 4 + i;
        #pragma unroll
        for (int j = 0; j < 4; j++) {
            const float v = O[i][j] * inv;
            const size_t idx = head_base + (size_t)q * DMODEL + tx * 4 + j;
            __nv_bfloat16 hi, lo; bf16_split(v, hi, lo);
            g_Zh[idx] = hi; g_Zl[idx] = lo;
        }
    }
}

// ------------------------------ launch --------------------------------------
extern "C" void kernel_launch(void* const* d_in, const int* in_sizes, int n_in,
                              void* d_out, int out_size)
{
    (void)in_sizes; (void)n_in; (void)out_size;
    const float* x  = (const float*)d_in[0];
    const float* Wq = (const float*)d_in[1];
    const float* Wk = (const float*)d_in[2];
    const float* Wv = (const float*)d_in[3];
    const float* Wo = (const float*)d_in[4];
    const float* bq = (const float*)d_in[5];
    const float* bk = (const float*)d_in[6];
    const float* bv = (const float*)d_in[7];
    const float* bo = (const float*)d_in[8];
    float* out = (float*)d_out;

    const int attn_smem = 4 * 64 * 65 * (int)sizeof(float);
    cudaFuncSetAttribute(attn_kernel,
                         cudaFuncAttributeMaxDynamicSharedMemorySize, attn_smem);

    convert_x_kernel<<<(MROWS * DMODEL / 2) / 256, 256>>>(x);
    transpose_wqkv<<<dim3(32, 2, 48), 256>>>(Wq, Wk, Wv);
    transpose_wo<<<dim3(32, 32), 256>>>(Wo);

    gemm_kernel<<<dim3(24, 32), 256>>>(bq, bk, bv, nullptr, 0);

    attn_kernel<<<dim3(SEQ / 64, NHEADS, BATCH), 256, attn_smem>>>();

    gemm_kernel<<<dim3(8, 32), 256>>>(bo, bo, bo, out, 1);
}

// round 12
// speedup vs baseline: 2.4846x; 1.9967x over previous
#include <cuda_runtime.h>
#include <cuda_bf16.h>
#include <cuda_fp16.h>
#include <stdint.h>
#include <math.h>

#define BATCH  2
#define SEQ    2048
#define NHEADS 16
#define DMODEL 1024
#define DHEAD  64
#define MROWS  (BATCH*SEQ)   // 4096

// ------------------------------ scratch ------------------------------------
// Only referenced from DEVICE code (host-side refs to __device__ symbols are
// garbage addresses — R8/R9 root cause).
__device__ __align__(16) __nv_bfloat16 g_xh[(size_t)MROWS * DMODEL];
__device__ __align__(16) __nv_bfloat16 g_xl[(size_t)MROWS * DMODEL];
__device__ __align__(16) __nv_bfloat16 g_Wh[(size_t)3 * DMODEL * DMODEL]; // [3072 n][1024 k]
__device__ __align__(16) __nv_bfloat16 g_Wl[(size_t)3 * DMODEL * DMODEL];
__device__ __align__(16) __nv_bfloat16 g_Woh[(size_t)DMODEL * DMODEL];    // [1024 d][1024 c]
__device__ __align__(16) __nv_bfloat16 g_Wol[(size_t)DMODEL * DMODEL];
__device__ __align__(16) __half g_Qf[(size_t)MROWS * DMODEL];  // [token][h*64+e], pre-scaled
__device__ __align__(16) __half g_Kf[(size_t)MROWS * DMODEL];  // [token][h*64+e]
__device__ __align__(16) __half g_Vt[(size_t)MROWS * DMODEL];  // [(b*16+h)*64+e][seq]
__device__ __align__(16) __nv_bfloat16 g_Zh[(size_t)MROWS * DMODEL];
__device__ __align__(16) __nv_bfloat16 g_Zl[(size_t)MROWS * DMODEL];

// ------------------------------ helpers ------------------------------------
__device__ __forceinline__ void mma_bf16(float c[4], const uint32_t a[4],
                                         uint32_t b0, uint32_t b1) {
    asm volatile(
        "mma.sync.aligned.m16n8k16.row.col.f32.bf16.bf16.f32 "
        "{%0,%1,%2,%3}, {%4,%5,%6,%7}, {%8,%9}, {%0,%1,%2,%3};"
        : "+f"(c[0]), "+f"(c[1]), "+f"(c[2]), "+f"(c[3])
        : "r"(a[0]), "r"(a[1]), "r"(a[2]), "r"(a[3]), "r"(b0), "r"(b1));
}
__device__ __forceinline__ void mma_f16(float c[4], const uint32_t a[4],
                                        uint32_t b0, uint32_t b1) {
    asm volatile(
        "mma.sync.aligned.m16n8k16.row.col.f32.f16.f16.f32 "
        "{%0,%1,%2,%3}, {%4,%5,%6,%7}, {%8,%9}, {%0,%1,%2,%3};"
        : "+f"(c[0]), "+f"(c[1]), "+f"(c[2]), "+f"(c[3])
        : "r"(a[0]), "r"(a[1]), "r"(a[2]), "r"(a[3]), "r"(b0), "r"(b1));
}
__device__ __forceinline__ void bf16_split(float v, __nv_bfloat16& hi, __nv_bfloat16& lo) {
    hi = __float2bfloat16(v);
    lo = __float2bfloat16(v - __bfloat162float(hi));
}
__device__ __forceinline__ uint32_t pack_h2(float a, float b) {
    __half2 h = __floats2half2_rn(a, b);
    return *(uint32_t*)&h;
}

// ------------------------- prep kernels -------------------------------------
__global__ __launch_bounds__(256) void convert_x_kernel(const float* __restrict__ x)
{
    int i = blockIdx.x * 256 + threadIdx.x;   // over MROWS*DMODEL/2
    float2 v = ((const float2*)x)[i];
    __nv_bfloat162 h, l;
    bf16_split(v.x, h.x, l.x);
    bf16_split(v.y, h.y, l.y);
    ((__nv_bfloat162*)g_xh)[i] = h;
    ((__nv_bfloat162*)g_xl)[i] = l;
}

// W_{Q,K,V}[h][k][e] -> g_Wh/g_Wl[(mat*1024 + h*64 + e)][k]  (z = mat*16+h)
__global__ __launch_bounds__(256) void transpose_wqkv(
    const float* __restrict__ Wq, const float* __restrict__ Wk,
    const float* __restrict__ Wv)
{
    const int z = blockIdx.z, mat = z >> 4, h = z & 15;
    const float* W = ((mat == 0) ? Wq : (mat == 1) ? Wk : Wv) + (size_t)h * DMODEL * DHEAD;
    __shared__ float t[32][33];
    const int k0 = blockIdx.x * 32, e0 = blockIdx.y * 32;
    const int tx = threadIdx.x & 31, ty = threadIdx.x >> 5;
    #pragma unroll
    for (int r = 0; r < 32; r += 8)
        t[ty + r][tx] = W[(size_t)(k0 + ty + r) * DHEAD + e0 + tx];
    __syncthreads();
    const int nbase = mat * 1024 + h * 64 + e0;
    #pragma unroll
    for (int r = 0; r < 32; r += 8) {
        float v = t[tx][ty + r];
        __nv_bfloat16 hi, lo; bf16_split(v, hi, lo);
        size_t idx = (size_t)(nbase + ty + r) * DMODEL + k0 + tx;
        g_Wh[idx] = hi; g_Wl[idx] = lo;
    }
}

// W_O flat [1024 c][1024 d] -> g_Woh/g_Wol[d][c]
__global__ __launch_bounds__(256) void transpose_wo(const float* __restrict__ Wo)
{
    __shared__ float t[32][33];
    const int d0 = blockIdx.x * 32, c0 = blockIdx.y * 32;
    const int tx = threadIdx.x & 31, ty = threadIdx.x >> 5;
    #pragma unroll
    for (int r = 0; r < 32; r += 8)
        t[ty + r][tx] = Wo[(size_t)(c0 + ty + r) * DMODEL + d0 + tx];
    __syncthreads();
    #pragma unroll
    for (int r = 0; r < 32; r += 8) {
        float v = t[tx][ty + r];
        __nv_bfloat16 hi, lo; bf16_split(v, hi, lo);
        size_t idx = (size_t)(d0 + ty + r) * DMODEL + c0 + tx;
        g_Woh[idx] = hi; g_Wol[idx] = lo;
    }
}

// ------------------- mma.sync bf16-split GEMM (proven body) -----------------
// mode 0: QKV  (A = x-split, B = g_Wh/g_Wl [3072][1024]) -> g_Qf/g_Kf/g_Vt fp16
// mode 1: proj (A = Z-split, B = g_Woh/g_Wol)            -> outp fp32 + b_O
#define ASTR 40   // bf16 elements per smem row (20 words: conflict-free lanes)

__global__ __launch_bounds__(256) void gemm_kernel(
    const float* __restrict__ b0, const float* __restrict__ b1,
    const float* __restrict__ b2, float* __restrict__ outp, int mode)
{
    __shared__ __align__(16) __nv_bfloat16 As[128 * ASTR];
    __shared__ __align__(16) __nv_bfloat16 Bs[128 * ASTR];

    const int tid = threadIdx.x, wid = tid >> 5, lane = tid & 31;
    const int m0 = blockIdx.y * 128, n0 = blockIdx.x * 128;
    const int wm = (wid & 3) * 32, wn = (wid >> 2) * 64;
    const int g  = lane >> 2;            // fragment row group
    const int kq = (lane & 3) * 2;       // fragment k-pair offset

    const __nv_bfloat16 *ah, *al, *bh, *bl;
    if (mode == 0) { ah = g_xh; al = g_xl; bh = g_Wh;  bl = g_Wl;  }
    else           { ah = g_Zh; al = g_Zl; bh = g_Woh; bl = g_Wol; }
    const __nv_bfloat16* Ap[3] = {ah, al, ah};
    const __nv_bfloat16* Bp[3] = {bh, bh, bl};
    const int NC = 96;                   // 3 planes x 32 chunks of K=32

    const int lr0 = tid >> 2, lseg = (tid & 3) * 8;   // loader row, k offset

    uint4 av[2], bv[2];
    auto load_regs = [&](int c) {
        const int p = c >> 5, k0 = (c & 31) * 32;
        #pragma unroll
        for (int it = 0; it < 2; it++) {
            const int r = lr0 + it * 64;
            av[it] = *(const uint4*)(Ap[p] + (size_t)(m0 + r) * DMODEL + k0 + lseg);
            bv[it] = *(const uint4*)(Bp[p] + (size_t)(n0 + r) * DMODEL + k0 + lseg);
        }
    };
    auto store_smem = [&]() {
        #pragma unroll
        for (int it = 0; it < 2; it++) {
            const int r = lr0 + it * 64;
            *(uint4*)&As[r * ASTR + lseg] = av[it];
            *(uint4*)&Bs[r * ASTR + lseg] = bv[it];
        }
    };

    float C[2][8][4];
    #pragma unroll
    for (int i = 0; i < 2; i++)
        #pragma unroll
        for (int j = 0; j < 8; j++)
            #pragma unroll
            for (int q = 0; q < 4; q++) C[i][j][q] = 0.0f;

    load_regs(0);
    store_smem();
    __syncthreads();

    for (int c = 0; c < NC; c++) {
        if (c + 1 < NC) load_regs(c + 1);

        #pragma unroll
        for (int ks = 0; ks < 2; ks++) {
            const int kc = ks * 16 + kq;
            uint32_t ar[2][4];
            #pragma unroll
            for (int i = 0; i < 2; i++) {
                const int row = wm + i * 16 + g;
                ar[i][0] = *(const uint32_t*)&As[(row)     * ASTR + kc];
                ar[i][1] = *(const uint32_t*)&As[(row + 8) * ASTR + kc];
                ar[i][2] = *(const uint32_t*)&As[(row)     * ASTR + kc + 8];
                ar[i][3] = *(const uint32_t*)&As[(row + 8) * ASTR + kc + 8];
            }
            #pragma unroll
            for (int j = 0; j < 8; j++) {
                const int nrow = wn + j * 8 + g;
                const uint32_t bb0 = *(const uint32_t*)&Bs[nrow * ASTR + kc];
                const uint32_t bb1 = *(const uint32_t*)&Bs[nrow * ASTR + kc + 8];
                mma_bf16(C[0][j], ar[0], bb0, bb1);
                mma_bf16(C[1][j], ar[1], bb0, bb1);
            }
        }
        __syncthreads();
        if (c + 1 < NC) {
            store_smem();
            __syncthreads();
        }
    }

    // ----- epilogue -----
    const int er = m0 + wm + g;
    const int ec = wn + kq;

    if (mode == 1) {
        #pragma unroll
        for (int i = 0; i < 2; i++) {
            #pragma unroll
            for (int j = 0; j < 8; j++) {
                const int col = n0 + ec + j * 8;
                const float bx = b0[col], by = b0[col + 1];
                const int row = er + i * 16;
                *(float2*)&outp[(size_t)row * DMODEL + col] =
                    make_float2(C[i][j][0] + bx, C[i][j][1] + by);
                *(float2*)&outp[(size_t)(row + 8) * DMODEL + col] =
                    make_float2(C[i][j][2] + bx, C[i][j][3] + by);
            }
        }
        return;
    }

    const int mat  = n0 >> 10;
    const int col0 = n0 & 1023;
    const float scale = (mat == 0) ? 0.125f : 1.0f;
    const float* bias = (mat == 0) ? b0 : (mat == 1) ? b1 : b2;

    #pragma unroll
    for (int i = 0; i < 2; i++) {
        #pragma unroll
        for (int j = 0; j < 8; j++) {
            const int col = col0 + ec + j * 8;
            const float bx = bias[col], by = bias[col + 1];
            const int row0 = er + i * 16, row1 = row0 + 8;
            const float v00 = (C[i][j][0] + bx) * scale;
            const float v01 = (C[i][j][1] + by) * scale;
            const float v10 = (C[i][j][2] + bx) * scale;
            const float v11 = (C[i][j][3] + by) * scale;
            if (mat == 0) {
                *(__half2*)&g_Qf[(size_t)row0 * DMODEL + col] = __floats2half2_rn(v00, v01);
                *(__half2*)&g_Qf[(size_t)row1 * DMODEL + col] = __floats2half2_rn(v10, v11);
            } else if (mat == 1) {
                *(__half2*)&g_Kf[(size_t)row0 * DMODEL + col] = __floats2half2_rn(v00, v01);
                *(__half2*)&g_Kf[(size_t)row1 * DMODEL + col] = __floats2half2_rn(v10, v11);
            } else {
                // V transposed: [(b*16+h)*64+e][seq]
                const int bb = row0 >> 11, s0 = row0 & 2047, s1 = s0 + 8;
                const int hh = col >> 6, e = col & 63;
                const size_t base = ((size_t)((bb * NHEADS + hh) * 64 + e)) * SEQ;
                g_Vt[base + s0]       = __float2half(v00);
                g_Vt[base + SEQ + s0] = __float2half(v01);   // e+1
                g_Vt[base + s1]       = __float2half(v10);
                g_Vt[base + SEQ + s1] = __float2half(v11);
            }
        }
    }
}

// ------------------------- fp16 mma flash attention -------------------------
// CTA = (qt, h, b): 64 queries, 4 warps x 16 rows. S and P live in fragments.
#define QSTR 72   // fp16 elems per smem row (36 words: conflict-free frag loads)

__global__ __launch_bounds__(128) void attn_kernel()
{
    __shared__ __align__(16) __half Qs[64 * QSTR];
    __shared__ __align__(16) __half Ks[64 * QSTR];
    __shared__ __align__(16) __half Vs[64 * QSTR];   // Vt tile: [d][key]

    const int qt = blockIdx.x, h = blockIdx.y, b = blockIdx.z;
    const int tid = threadIdx.x, w = tid >> 5, lane = tid & 31;
    const int g = lane >> 2, kq = (lane & 3) * 2;
    const int q0 = qt * 64;

    // Q tile load: 64 rows x 8 16B-segs = 512 slots
    #pragma unroll
    for (int it = 0; it < 4; it++) {
        const int s = tid + it * 128, r = s >> 3, seg = s & 7;
        *(uint4*)&Qs[r * QSTR + seg * 8] =
            *(const uint4*)(g_Qf + (size_t)(b * SEQ + q0 + r) * DMODEL + h * 64 + seg * 8);
    }

    uint4 kvr[4], vvr[4];
    auto load_regs = [&](int kt) {
        const int k0 = kt * 64;
        #pragma unroll
        for (int it = 0; it < 4; it++) {
            const int s = tid + it * 128, r = s >> 3, seg = s & 7;
            kvr[it] = *(const uint4*)(g_Kf + (size_t)(b * SEQ + k0 + r) * DMODEL + h * 64 + seg * 8);
            vvr[it] = *(const uint4*)(g_Vt + ((size_t)((b * NHEADS + h) * 64 + r)) * SEQ + k0 + seg * 8);
        }
    };
    auto store_smem = [&]() {
        #pragma unroll
        for (int it = 0; it < 4; it++) {
            const int s = tid + it * 128, r = s >> 3, seg = s & 7;
            *(uint4*)&Ks[r * QSTR + seg * 8] = kvr[it];
            *(uint4*)&Vs[r * QSTR + seg * 8] = vvr[it];
        }
    };

    float m_run[2] = {-1e30f, -1e30f};
    float l_run[2] = {0.0f, 0.0f};
    float Z[8][4];
    #pragma unroll
    for (int j = 0; j < 8; j++)
        #pragma unroll
        for (int q = 0; q < 4; q++) Z[j][q] = 0.0f;

    load_regs(0);

    for (int kt = 0; kt <= qt; kt++) {
        store_smem();
        __syncthreads();
        if (kt < qt) load_regs(kt + 1);

        // ---- S = Q K^T ----
        float S[8][4];
        #pragma unroll
        for (int j = 0; j < 8; j++)
            #pragma unroll
            for (int q = 0; q < 4; q++) S[j][q] = 0.0f;

        #pragma unroll
        for (int ks = 0; ks < 4; ks++) {
            const int kc = ks * 16 + kq;
            const int row = w * 16 + g;
            uint32_t a[4];
            a[0] = *(const uint32_t*)&Qs[(row)     * QSTR + kc];
            a[1] = *(const uint32_t*)&Qs[(row + 8) * QSTR + kc];
            a[2] = *(const uint32_t*)&Qs[(row)     * QSTR + kc + 8];
            a[3] = *(const uint32_t*)&Qs[(row + 8) * QSTR + kc + 8];
            #pragma unroll
            for (int j = 0; j < 8; j++) {
                const int nrow = j * 8 + g;
                const uint32_t bb0 = *(const uint32_t*)&Ks[nrow * QSTR + kc];
                const uint32_t bb1 = *(const uint32_t*)&Ks[nrow * QSTR + kc + 8];
                mma_f16(S[j], a, bb0, bb1);
            }
        }

        // ---- causal mask (diagonal tile only) ----
        if (kt == qt) {
            const int r0 = w * 16 + g, r1 = r0 + 8;
            #pragma unroll
            for (int j = 0; j < 8; j++) {
                const int c0 = j * 8 + kq, c1 = c0 + 1;
                if (c0 > r0) S[j][0] = -1e30f;
                if (c1 > r0) S[j][1] = -1e30f;
                if (c0 > r1) S[j][2] = -1e30f;
                if (c1 > r1) S[j][3] = -1e30f;
            }
        }

        // ---- online softmax on fragments (rows r0, r1 per thread) ----
        float mx0 = -1e30f, mx1 = -1e30f;
        #pragma unroll
        for (int j = 0; j < 8; j++) {
            mx0 = fmaxf(mx0, fmaxf(S[j][0], S[j][1]));
            mx1 = fmaxf(mx1, fmaxf(S[j][2], S[j][3]));
        }
        mx0 = fmaxf(mx0, __shfl_xor_sync(0xffffffffu, mx0, 1));
        mx0 = fmaxf(mx0, __shfl_xor_sync(0xffffffffu, mx0, 2));
        mx1 = fmaxf(mx1, __shfl_xor_sync(0xffffffffu, mx1, 1));
        mx1 = fmaxf(mx1, __shfl_xor_sync(0xffffffffu, mx1, 2));

        const float mn0 = fmaxf(m_run[0], mx0);
        const float mn1 = fmaxf(m_run[1], mx1);
        const float al0 = __expf(m_run[0] - mn0);
        const float al1 = __expf(m_run[1] - mn1);
        float sum0 = 0.0f, sum1 = 0.0f;
        #pragma unroll
        for (int j = 0; j < 8; j++) {
            S[j][0] = __expf(S[j][0] - mn0); sum0 += S[j][0];
            S[j][1] = __expf(S[j][1] - mn0); sum0 += S[j][1];
            S[j][2] = __expf(S[j][2] - mn1); sum1 += S[j][2];
            S[j][3] = __expf(S[j][3] - mn1); sum1 += S[j][3];
        }
        sum0 += __shfl_xor_sync(0xffffffffu, sum0, 1);
        sum0 += __shfl_xor_sync(0xffffffffu, sum0, 2);
        sum1 += __shfl_xor_sync(0xffffffffu, sum1, 1);
        sum1 += __shfl_xor_sync(0xffffffffu, sum1, 2);

        l_run[0] = l_run[0] * al0 + sum0;  m_run[0] = mn0;
        l_run[1] = l_run[1] * al1 + sum1;  m_run[1] = mn1;

        #pragma unroll
        for (int j = 0; j < 8; j++) {
            Z[j][0] *= al0; Z[j][1] *= al0;
            Z[j][2] *= al1; Z[j][3] *= al1;
        }

        // ---- Z += P V : repack S c-frags into a-frags (pure register) ----
        #pragma unroll
        for (int jj = 0; jj < 4; jj++) {
            uint32_t a[4];
            a[0] = pack_h2(S[2*jj][0],     S[2*jj][1]);
            a[1] = pack_h2(S[2*jj][2],     S[2*jj][3]);
            a[2] = pack_h2(S[2*jj + 1][0], S[2*jj + 1][1]);
            a[3] = pack_h2(S[2*jj + 1][2], S[2*jj + 1][3]);
            const int kc = jj * 16 + kq;
            #pragma unroll
            for (int j = 0; j < 8; j++) {
                const int nrow = j * 8 + g;
                const uint32_t bb0 = *(const uint32_t*)&Vs[nrow * QSTR + kc];
                const uint32_t bb1 = *(const uint32_t*)&Vs[nrow * QSTR + kc + 8];
                mma_f16(Z[j], a, bb0, bb1);
            }
        }
        __syncthreads();
    }

    // ---- epilogue: normalize + split-bf16 Z ----
    const float inv0 = 1.0f / l_run[0];
    const float inv1 = 1.0f / l_run[1];
    const int r0 = q0 + w * 16 + g, r1 = r0 + 8;
    #pragma unroll
    for (int j = 0; j < 8; j++) {
        const int col = h * 64 + j * 8 + kq;
        const size_t i0 = (size_t)(b * SEQ + r0) * DMODEL + col;
        const size_t i1 = (size_t)(b * SEQ + r1) * DMODEL + col;
        __nv_bfloat16 hi, lo;
        bf16_split(Z[j][0] * inv0, hi, lo); g_Zh[i0]     = hi; g_Zl[i0]     = lo;
        bf16_split(Z[j][1] * inv0, hi, lo); g_Zh[i0 + 1] = hi; g_Zl[i0 + 1] = lo;
        bf16_split(Z[j][2] * inv1, hi, lo); g_Zh[i1]     = hi; g_Zl[i1]     = lo;
        bf16_split(Z[j][3] * inv1, hi, lo); g_Zh[i1 + 1] = hi; g_Zl[i1 + 1] = lo;
    }
}

// ------------------------------ launch --------------------------------------
extern "C" void kernel_launch(void* const* d_in, const int* in_sizes, int n_in,
                              void* d_out, int out_size)
{
    (void)in_sizes; (void)n_in; (void)out_size;
    const float* x  = (const float*)d_in[0];
    const float* Wq = (const float*)d_in[1];
    const float* Wk = (const float*)d_in[2];
    const float* Wv = (const float*)d_in[3];
    const float* Wo = (const float*)d_in[4];
    const float* bq = (const float*)d_in[5];
    const float* bk = (const float*)d_in[6];
    const float* bv = (const float*)d_in[7];
    const float* bo = (const float*)d_in[8];
    float* out = (float*)d_out;

    convert_x_kernel<<<(MROWS * DMODEL / 2) / 256, 256>>>(x);
    transpose_wqkv<<<dim3(32, 2, 48), 256>>>(Wq, Wk, Wv);
    transpose_wo<<<dim3(32, 32), 256>>>(Wo);

    gemm_kernel<<<dim3(24, 32), 256>>>(bq, bk, bv, nullptr, 0);

    attn_kernel<<<dim3(SEQ / 64, NHEADS, BATCH), 128>>>();

    gemm_kernel<<<dim3(8, 32), 256>>>(bo, bo, bo, out, 1);
}

// round 13
// speedup vs baseline: 2.8855x; 1.1613x over previous
#include <cuda_runtime.h>
#include <cuda_bf16.h>
#include <cuda_fp16.h>
#include <stdint.h>
#include <math.h>

#define BATCH  2
#define SEQ    2048
#define NHEADS 16
#define DMODEL 1024
#define DHEAD  64
#define MROWS  (BATCH*SEQ)   // 4096

// ------------------------------ scratch ------------------------------------
// Only referenced from DEVICE code (host-side refs to __device__ symbols are
// garbage addresses — R8/R9 root cause).
__device__ __align__(16) __nv_bfloat16 g_xh[(size_t)MROWS * DMODEL];
__device__ __align__(16) __nv_bfloat16 g_xl[(size_t)MROWS * DMODEL];
__device__ __align__(16) __nv_bfloat16 g_Wh[(size_t)3 * DMODEL * DMODEL]; // [3072 n][1024 k]
__device__ __align__(16) __nv_bfloat16 g_Wl[(size_t)3 * DMODEL * DMODEL];
__device__ __align__(16) __nv_bfloat16 g_Woh[(size_t)DMODEL * DMODEL];    // [1024 d][1024 c]
__device__ __align__(16) __nv_bfloat16 g_Wol[(size_t)DMODEL * DMODEL];
__device__ __align__(16) __half g_Qf[(size_t)MROWS * DMODEL];  // [token][h*64+e], pre-scaled
__device__ __align__(16) __half g_Kf[(size_t)MROWS * DMODEL];  // [token][h*64+e]
__device__ __align__(16) __half g_Vt[(size_t)MROWS * DMODEL];  // [(b*16+h)*64+e][seq]
__device__ __align__(16) __nv_bfloat16 g_Zh[(size_t)MROWS * DMODEL];
__device__ __align__(16) __nv_bfloat16 g_Zl[(size_t)MROWS * DMODEL];

// ------------------------------ helpers ------------------------------------
__device__ __forceinline__ uint32_t smem_u32(const void* p) {
    uint32_t a;
    asm("{ .reg .u64 t; cvta.to.shared.u64 t, %1; cvt.u32.u64 %0, t; }"
        : "=r"(a) : "l"(p));
    return a;
}
#define CP_ASYNC16(dst, src) \
    asm volatile("cp.async.cg.shared.global [%0], [%1], 16;" :: "r"(dst), "l"(src))
#define CP_COMMIT() asm volatile("cp.async.commit_group;" ::: "memory")

__device__ __forceinline__ void ldsm4(uint32_t r[4], uint32_t addr) {
    asm volatile("ldmatrix.sync.aligned.m8n8.x4.shared.b16 {%0,%1,%2,%3}, [%4];"
        : "=r"(r[0]), "=r"(r[1]), "=r"(r[2]), "=r"(r[3]) : "r"(addr));
}
__device__ __forceinline__ void mma_bf16(float c[4], const uint32_t a[4],
                                         uint32_t b0, uint32_t b1) {
    asm volatile(
        "mma.sync.aligned.m16n8k16.row.col.f32.bf16.bf16.f32 "
        "{%0,%1,%2,%3}, {%4,%5,%6,%7}, {%8,%9}, {%0,%1,%2,%3};"
        : "+f"(c[0]), "+f"(c[1]), "+f"(c[2]), "+f"(c[3])
        : "r"(a[0]), "r"(a[1]), "r"(a[2]), "r"(a[3]), "r"(b0), "r"(b1));
}
__device__ __forceinline__ void mma_f16(float c[4], const uint32_t a[4],
                                        uint32_t b0, uint32_t b1) {
    asm volatile(
        "mma.sync.aligned.m16n8k16.row.col.f32.f16.f16.f32 "
        "{%0,%1,%2,%3}, {%4,%5,%6,%7}, {%8,%9}, {%0,%1,%2,%3};"
        : "+f"(c[0]), "+f"(c[1]), "+f"(c[2]), "+f"(c[3])
        : "r"(a[0]), "r"(a[1]), "r"(a[2]), "r"(a[3]), "r"(b0), "r"(b1));
}
__device__ __forceinline__ void bf16_split(float v, __nv_bfloat16& hi, __nv_bfloat16& lo) {
    hi = __float2bfloat16(v);
    lo = __float2bfloat16(v - __bfloat162float(hi));
}
__device__ __forceinline__ uint32_t pack_h2(float a, float b) {
    __half2 h = __floats2half2_rn(a, b);
    return *(uint32_t*)&h;
}

// ------------------------- prep kernels -------------------------------------
__global__ __launch_bounds__(256) void convert_x_kernel(const float* __restrict__ x)
{
    int i = blockIdx.x * 256 + threadIdx.x;   // over MROWS*DMODEL/2
    float2 v = ((const float2*)x)[i];
    __nv_bfloat162 h, l;
    bf16_split(v.x, h.x, l.x);
    bf16_split(v.y, h.y, l.y);
    ((__nv_bfloat162*)g_xh)[i] = h;
    ((__nv_bfloat162*)g_xl)[i] = l;
}

// W_{Q,K,V}[h][k][e] -> g_Wh/g_Wl[(mat*1024 + h*64 + e)][k]  (z = mat*16+h)
__global__ __launch_bounds__(256) void transpose_wqkv(
    const float* __restrict__ Wq, const float* __restrict__ Wk,
    const float* __restrict__ Wv)
{
    const int z = blockIdx.z, mat = z >> 4, h = z & 15;
    const float* W = ((mat == 0) ? Wq : (mat == 1) ? Wk : Wv) + (size_t)h * DMODEL * DHEAD;
    __shared__ float t[32][33];
    const int k0 = blockIdx.x * 32, e0 = blockIdx.y * 32;
    const int tx = threadIdx.x & 31, ty = threadIdx.x >> 5;
    #pragma unroll
    for (int r = 0; r < 32; r += 8)
        t[ty + r][tx] = W[(size_t)(k0 + ty + r) * DHEAD + e0 + tx];
    __syncthreads();
    const int nbase = mat * 1024 + h * 64 + e0;
    #pragma unroll
    for (int r = 0; r < 32; r += 8) {
        float v = t[tx][ty + r];
        __nv_bfloat16 hi, lo; bf16_split(v, hi, lo);
        size_t idx = (size_t)(nbase + ty + r) * DMODEL + k0 + tx;
        g_Wh[idx] = hi; g_Wl[idx] = lo;
    }
}

// W_O flat [1024 c][1024 d] -> g_Woh/g_Wol[d][c]
__global__ __launch_bounds__(256) void transpose_wo(const float* __restrict__ Wo)
{
    __shared__ float t[32][33];
    const int d0 = blockIdx.x * 32, c0 = blockIdx.y * 32;
    const int tx = threadIdx.x & 31, ty = threadIdx.x >> 5;
    #pragma unroll
    for (int r = 0; r < 32; r += 8)
        t[ty + r][tx] = Wo[(size_t)(c0 + ty + r) * DMODEL + d0 + tx];
    __syncthreads();
    #pragma unroll
    for (int r = 0; r < 32; r += 8) {
        float v = t[tx][ty + r];
        __nv_bfloat16 hi, lo; bf16_split(v, hi, lo);
        size_t idx = (size_t)(d0 + ty + r) * DMODEL + c0 + tx;
        g_Woh[idx] = hi; g_Wol[idx] = lo;
    }
}

// --------------- mma.sync bf16-split GEMM (cp.async + ldmatrix) -------------
// D[128,128] = sum over 3 plane-pairs of A[m][k]*B[n][k]^T, K=1024 each.
// mode 0: QKV  (A = x-split, B = g_Wh/g_Wl [3072][1024]) -> g_Qf/g_Kf/g_Vt fp16
// mode 1: proj (A = Z-split, B = g_Woh/g_Wol)            -> outp fp32 + b_O
#define ASTR 40   // bf16 elements per smem row (80B: ldmatrix phase-disjoint banks)

__global__ __launch_bounds__(256) void gemm_kernel(
    const float* __restrict__ b0, const float* __restrict__ b1,
    const float* __restrict__ b2, float* __restrict__ outp, int mode)
{
    __shared__ __align__(16) __nv_bfloat16 As[2][128 * ASTR];
    __shared__ __align__(16) __nv_bfloat16 Bs[2][128 * ASTR];

    const int tid = threadIdx.x, wid = tid >> 5, lane = tid & 31;
    const int m0 = blockIdx.y * 128, n0 = blockIdx.x * 128;
    const int wm = (wid & 3) * 32, wn = (wid >> 2) * 64;
    const int g  = lane >> 2;            // fragment row group
    const int kq = (lane & 3) * 2;       // fragment k-pair offset

    const uint32_t sA[2] = {smem_u32(&As[0][0]), smem_u32(&As[1][0])};
    const uint32_t sB[2] = {smem_u32(&Bs[0][0]), smem_u32(&Bs[1][0])};

    const __nv_bfloat16 *ah, *al, *bh, *bl;
    if (mode == 0) { ah = g_xh; al = g_xl; bh = g_Wh;  bl = g_Wl;  }
    else           { ah = g_Zh; al = g_Zl; bh = g_Woh; bl = g_Wol; }
    const __nv_bfloat16* Ap[3] = {ah, al, ah};
    const __nv_bfloat16* Bp[3] = {bh, bh, bl};
    const int NC = 96;                   // 3 planes x 32 chunks of K=32

    const int lr0 = tid >> 2, lseg = (tid & 3) * 8;   // loader row, k offset

    auto load_chunk = [&](int buf, int c) {
        const int p = c >> 5, k0 = (c & 31) * 32;
        const __nv_bfloat16* a = Ap[p];
        const __nv_bfloat16* b = Bp[p];
        #pragma unroll
        for (int it = 0; it < 2; it++) {
            const int r = lr0 + it * 64;
            CP_ASYNC16(sA[buf] + (r * ASTR + lseg) * 2,
                       a + (size_t)(m0 + r) * DMODEL + k0 + lseg);
            CP_ASYNC16(sB[buf] + (r * ASTR + lseg) * 2,
                       b + (size_t)(n0 + r) * DMODEL + k0 + lseg);
        }
        CP_COMMIT();
    };

    float C[2][8][4];
    #pragma unroll
    for (int i = 0; i < 2; i++)
        #pragma unroll
        for (int j = 0; j < 8; j++)
            #pragma unroll
            for (int q = 0; q < 4; q++) C[i][j][q] = 0.0f;

    // ldmatrix per-lane address pieces: row-in-16 = lane&15, k-half = (lane>>4)*8
    const int lrow = lane & 15, lcol = (lane >> 4) * 8;

    load_chunk(0, 0);

    for (int c = 0; c < NC; c++) {
        const int buf = c & 1;
        if (c + 1 < NC) {
            load_chunk(buf ^ 1, c + 1);
            asm volatile("cp.async.wait_group 1;" ::: "memory");
        } else {
            asm volatile("cp.async.wait_group 0;" ::: "memory");
        }
        __syncthreads();

        #pragma unroll
        for (int ks = 0; ks < 2; ks++) {
            uint32_t ar[2][4];
            #pragma unroll
            for (int i = 0; i < 2; i++)
                ldsm4(ar[i], sA[buf] +
                      ((wm + i * 16 + lrow) * ASTR + ks * 16 + lcol) * 2);
            uint32_t br[4][4];
            #pragma unroll
            for (int j16 = 0; j16 < 4; j16++)
                ldsm4(br[j16], sB[buf] +
                      ((wn + j16 * 16 + lrow) * ASTR + ks * 16 + lcol) * 2);
            #pragma unroll
            for (int i = 0; i < 2; i++)
                #pragma unroll
                for (int j = 0; j < 8; j++)
                    mma_bf16(C[i][j], ar[i], br[j >> 1][j & 1], br[j >> 1][(j & 1) + 2]);
        }
        __syncthreads();
    }

    // ----- epilogue -----
    const int er = m0 + wm + g;
    const int ec = wn + kq;

    if (mode == 1) {
        #pragma unroll
        for (int i = 0; i < 2; i++) {
            #pragma unroll
            for (int j = 0; j < 8; j++) {
                const int col = n0 + ec + j * 8;
                const float bx = b0[col], by = b0[col + 1];
                const int row = er + i * 16;
                *(float2*)&outp[(size_t)row * DMODEL + col] =
                    make_float2(C[i][j][0] + bx, C[i][j][1] + by);
                *(float2*)&outp[(size_t)(row + 8) * DMODEL + col] =
                    make_float2(C[i][j][2] + bx, C[i][j][3] + by);
            }
        }
        return;
    }

    const int mat  = n0 >> 10;
    const int col0 = n0 & 1023;
    const float scale = (mat == 0) ? 0.125f : 1.0f;
    const float* bias = (mat == 0) ? b0 : (mat == 1) ? b1 : b2;

    #pragma unroll
    for (int i = 0; i < 2; i++) {
        #pragma unroll
        for (int j = 0; j < 8; j++) {
            const int col = col0 + ec + j * 8;
            const float bx = bias[col], by = bias[col + 1];
            const int row0 = er + i * 16, row1 = row0 + 8;
            const float v00 = (C[i][j][0] + bx) * scale;
            const float v01 = (C[i][j][1] + by) * scale;
            const float v10 = (C[i][j][2] + bx) * scale;
            const float v11 = (C[i][j][3] + by) * scale;
            if (mat == 0) {
                *(__half2*)&g_Qf[(size_t)row0 * DMODEL + col] = __floats2half2_rn(v00, v01);
                *(__half2*)&g_Qf[(size_t)row1 * DMODEL + col] = __floats2half2_rn(v10, v11);
            } else if (mat == 1) {
                *(__half2*)&g_Kf[(size_t)row0 * DMODEL + col] = __floats2half2_rn(v00, v01);
                *(__half2*)&g_Kf[(size_t)row1 * DMODEL + col] = __floats2half2_rn(v10, v11);
            } else {
                // V transposed: [(b*16+h)*64+e][seq]
                const int bb = row0 >> 11, s0 = row0 & 2047, s1 = s0 + 8;
                const int hh = col >> 6, e = col & 63;
                const size_t base = ((size_t)((bb * NHEADS + hh) * 64 + e)) * SEQ;
                g_Vt[base + s0]       = __float2half(v00);
                g_Vt[base + SEQ + s0] = __float2half(v01);   // e+1
                g_Vt[base + s1]       = __float2half(v10);
                g_Vt[base + SEQ + s1] = __float2half(v11);
            }
        }
    }
}

// ------------------------- fp16 mma flash attention -------------------------
// CTA = (qt, h, b): 64 queries, 4 warps x 16 rows. S and P live in fragments.
#define QSTR 72   // fp16 elems per smem row (36 words: conflict-free frag loads)

__global__ __launch_bounds__(128) void attn_kernel()
{
    __shared__ __align__(16) __half Qs[64 * QSTR];
    __shared__ __align__(16) __half Ks[64 * QSTR];
    __shared__ __align__(16) __half Vs[64 * QSTR];   // Vt tile: [d][key]

    const int qt = blockIdx.x, h = blockIdx.y, b = blockIdx.z;
    const int tid = threadIdx.x, w = tid >> 5, lane = tid & 31;
    const int g = lane >> 2, kq = (lane & 3) * 2;
    const int q0 = qt * 64;

    // Q tile load: 64 rows x 8 16B-segs = 512 slots
    #pragma unroll
    for (int it = 0; it < 4; it++) {
        const int s = tid + it * 128, r = s >> 3, seg = s & 7;
        *(uint4*)&Qs[r * QSTR + seg * 8] =
            *(const uint4*)(g_Qf + (size_t)(b * SEQ + q0 + r) * DMODEL + h * 64 + seg * 8);
    }

    uint4 kvr[4], vvr[4];
    auto load_regs = [&](int kt) {
        const int k0 = kt * 64;
        #pragma unroll
        for (int it = 0; it < 4; it++) {
            const int s = tid + it * 128, r = s >> 3, seg = s & 7;
            kvr[it] = *(const uint4*)(g_Kf + (size_t)(b * SEQ + k0 + r) * DMODEL + h * 64 + seg * 8);
            vvr[it] = *(const uint4*)(g_Vt + ((size_t)((b * NHEADS + h) * 64 + r)) * SEQ + k0 + seg * 8);
        }
    };
    auto store_smem = [&]() {
        #pragma unroll
        for (int it = 0; it < 4; it++) {
            const int s = tid + it * 128, r = s >> 3, seg = s & 7;
            *(uint4*)&Ks[r * QSTR + seg * 8] = kvr[it];
            *(uint4*)&Vs[r * QSTR + seg * 8] = vvr[it];
        }
    };

    float m_run[2] = {-1e30f, -1e30f};
    float l_run[2] = {0.0f, 0.0f};
    float Z[8][4];
    #pragma unroll
    for (int j = 0; j < 8; j++)
        #pragma unroll
        for (int q = 0; q < 4; q++) Z[j][q] = 0.0f;

    load_regs(0);

    for (int kt = 0; kt <= qt; kt++) {
        store_smem();
        __syncthreads();
        if (kt < qt) load_regs(kt + 1);

        // ---- S = Q K^T ----
        float S[8][4];
        #pragma unroll
        for (int j = 0; j < 8; j++)
            #pragma unroll
            for (int q = 0; q < 4; q++) S[j][q] = 0.0f;

        #pragma unroll
        for (int ks = 0; ks < 4; ks++) {
            const int kc = ks * 16 + kq;
            const int row = w * 16 + g;
            uint32_t a[4];
            a[0] = *(const uint32_t*)&Qs[(row)     * QSTR + kc];
            a[1] = *(const uint32_t*)&Qs[(row + 8) * QSTR + kc];
            a[2] = *(const uint32_t*)&Qs[(row)     * QSTR + kc + 8];
            a[3] = *(const uint32_t*)&Qs[(row + 8) * QSTR + kc + 8];
            #pragma unroll
            for (int j = 0; j < 8; j++) {
                const int nrow = j * 8 + g;
                const uint32_t bb0 = *(const uint32_t*)&Ks[nrow * QSTR + kc];
                const uint32_t bb1 = *(const uint32_t*)&Ks[nrow * QSTR + kc + 8];
                mma_f16(S[j], a, bb0, bb1);
            }
        }

        // ---- causal mask (diagonal tile only) ----
        if (kt == qt) {
            const int r0 = w * 16 + g, r1 = r0 + 8;
            #pragma unroll
            for (int j = 0; j < 8; j++) {
                const int c0 = j * 8 + kq, c1 = c0 + 1;
                if (c0 > r0) S[j][0] = -1e30f;
                if (c1 > r0) S[j][1] = -1e30f;
                if (c0 > r1) S[j][2] = -1e30f;
                if (c1 > r1) S[j][3] = -1e30f;
            }
        }

        // ---- online softmax on fragments (rows r0, r1 per thread) ----
        float mx0 = -1e30f, mx1 = -1e30f;
        #pragma unroll
        for (int j = 0; j < 8; j++) {
            mx0 = fmaxf(mx0, fmaxf(S[j][0], S[j][1]));
            mx1 = fmaxf(mx1, fmaxf(S[j][2], S[j][3]));
        }
        mx0 = fmaxf(mx0, __shfl_xor_sync(0xffffffffu, mx0, 1));
        mx0 = fmaxf(mx0, __shfl_xor_sync(0xffffffffu, mx0, 2));
        mx1 = fmaxf(mx1, __shfl_xor_sync(0xffffffffu, mx1, 1));
        mx1 = fmaxf(mx1, __shfl_xor_sync(0xffffffffu, mx1, 2));

        const float mn0 = fmaxf(m_run[0], mx0);
        const float mn1 = fmaxf(m_run[1], mx1);
        const float al0 = __expf(m_run[0] - mn0);
        const float al1 = __expf(m_run[1] - mn1);
        float sum0 = 0.0f, sum1 = 0.0f;
        #pragma unroll
        for (int j = 0; j < 8; j++) {
            S[j][0] = __expf(S[j][0] - mn0); sum0 += S[j][0];
            S[j][1] = __expf(S[j][1] - mn0); sum0 += S[j][1];
            S[j][2] = __expf(S[j][2] - mn1); sum1 += S[j][2];
            S[j][3] = __expf(S[j][3] - mn1); sum1 += S[j][3];
        }
        sum0 += __shfl_xor_sync(0xffffffffu, sum0, 1);
        sum0 += __shfl_xor_sync(0xffffffffu, sum0, 2);
        sum1 += __shfl_xor_sync(0xffffffffu, sum1, 1);
        sum1 += __shfl_xor_sync(0xffffffffu, sum1, 2);

        l_run[0] = l_run[0] * al0 + sum0;  m_run[0] = mn0;
        l_run[1] = l_run[1] * al1 + sum1;  m_run[1] = mn1;

        #pragma unroll
        for (int j = 0; j < 8; j++) {
            Z[j][0] *= al0; Z[j][1] *= al0;
            Z[j][2] *= al1; Z[j][3] *= al1;
        }

        // ---- Z += P V : repack S c-frags into a-frags (pure register) ----
        #pragma unroll
        for (int jj = 0; jj < 4; jj++) {
            uint32_t a[4];
            a[0] = pack_h2(S[2*jj][0],     S[2*jj][1]);
            a[1] = pack_h2(S[2*jj][2],     S[2*jj][3]);
            a[2] = pack_h2(S[2*jj + 1][0], S[2*jj + 1][1]);
            a[3] = pack_h2(S[2*jj + 1][2], S[2*jj + 1][3]);
            const int kc = jj * 16 + kq;
            #pragma unroll
            for (int j = 0; j < 8; j++) {
                const int nrow = j * 8 + g;
                const uint32_t bb0 = *(const uint32_t*)&Vs[nrow * QSTR + kc];
                const uint32_t bb1 = *(const uint32_t*)&Vs[nrow * QSTR + kc + 8];
                mma_f16(Z[j], a, bb0, bb1);
            }
        }
        __syncthreads();
    }

    // ---- epilogue: normalize + split-bf16 Z ----
    const float inv0 = 1.0f / l_run[0];
    const float inv1 = 1.0f / l_run[1];
    const int r0 = q0 + w * 16 + g, r1 = r0 + 8;
    #pragma unroll
    for (int j = 0; j < 8; j++) {
        const int col = h * 64 + j * 8 + kq;
        const size_t i0 = (size_t)(b * SEQ + r0) * DMODEL + col;
        const size_t i1 = (size_t)(b * SEQ + r1) * DMODEL + col;
        __nv_bfloat16 hi, lo;
        bf16_split(Z[j][0] * inv0, hi, lo); g_Zh[i0]     = hi; g_Zl[i0]     = lo;
        bf16_split(Z[j][1] * inv0, hi, lo); g_Zh[i0 + 1] = hi; g_Zl[i0 + 1] = lo;
        bf16_split(Z[j][2] * inv1, hi, lo); g_Zh[i1]     = hi; g_Zl[i1]     = lo;
        bf16_split(Z[j][3] * inv1, hi, lo); g_Zh[i1 + 1] = hi; g_Zl[i1 + 1] = lo;
    }
}

// ------------------------------ launch --------------------------------------
extern "C" void kernel_launch(void* const* d_in, const int* in_sizes, int n_in,
                              void* d_out, int out_size)
{
    (void)in_sizes; (void)n_in; (void)out_size;
    const float* x  = (const float*)d_in[0];
    const float* Wq = (const float*)d_in[1];
    const float* Wk = (const float*)d_in[2];
    const float* Wv = (const float*)d_in[3];
    const float* Wo = (const float*)d_in[4];
    const float* bq = (const float*)d_in[5];
    const float* bk = (const float*)d_in[6];
    const float* bv = (const float*)d_in[7];
    const float* bo = (const float*)d_in[8];
    float* out = (float*)d_out;

    convert_x_kernel<<<(MROWS * DMODEL / 2) / 256, 256>>>(x);
    transpose_wqkv<<<dim3(32, 2, 48), 256>>>(Wq, Wk, Wv);
    transpose_wo<<<dim3(32, 32), 256>>>(Wo);

    gemm_kernel<<<dim3(24, 32), 256>>>(bq, bk, bv, nullptr, 0);

    attn_kernel<<<dim3(SEQ / 64, NHEADS, BATCH), 128>>>();

    gemm_kernel<<<dim3(8, 32), 256>>>(bo, bo, bo, out, 1);
}

// round 14
// speedup vs baseline: 3.3312x; 1.1545x over previous
#include <cuda_runtime.h>
#include <cuda_bf16.h>
#include <cuda_fp16.h>
#include <stdint.h>
#include <math.h>

#define BATCH  2
#define SEQ    2048
#define NHEADS 16
#define DMODEL 1024
#define DHEAD  64
#define MROWS  (BATCH*SEQ)   // 4096

// ------------------------------ scratch ------------------------------------
// Only referenced from DEVICE code (host-side refs to __device__ symbols are
// garbage addresses — R8/R9 root cause).
__device__ __align__(16) __nv_bfloat16 g_xh[(size_t)MROWS * DMODEL];
__device__ __align__(16) __nv_bfloat16 g_xl[(size_t)MROWS * DMODEL];
__device__ __align__(16) __nv_bfloat16 g_Wh[(size_t)3 * DMODEL * DMODEL]; // [3072 n][1024 k]
__device__ __align__(16) __nv_bfloat16 g_Wl[(size_t)3 * DMODEL * DMODEL];
__device__ __align__(16) __nv_bfloat16 g_Woh[(size_t)DMODEL * DMODEL];    // [1024 d][1024 c]
__device__ __align__(16) __nv_bfloat16 g_Wol[(size_t)DMODEL * DMODEL];
__device__ __align__(16) __half g_Qf[(size_t)MROWS * DMODEL];  // [token][h*64+e], pre-scaled
__device__ __align__(16) __half g_Kf[(size_t)MROWS * DMODEL];  // [token][h*64+e]
__device__ __align__(16) __half g_Vt[(size_t)MROWS * DMODEL];  // [(b*16+h)*64+e][seq]
__device__ __align__(16) __nv_bfloat16 g_Zh[(size_t)MROWS * DMODEL];
__device__ __align__(16) __nv_bfloat16 g_Zl[(size_t)MROWS * DMODEL];

// ------------------------------ helpers ------------------------------------
__device__ __forceinline__ uint32_t smem_u32(const void* p) {
    uint32_t a;
    asm("{ .reg .u64 t; cvta.to.shared.u64 t, %1; cvt.u32.u64 %0, t; }"
        : "=r"(a) : "l"(p));
    return a;
}
#define CP_ASYNC16(dst, src) \
    asm volatile("cp.async.cg.shared.global [%0], [%1], 16;" :: "r"(dst), "l"(src))
#define CP_COMMIT() asm volatile("cp.async.commit_group;" ::: "memory")

__device__ __forceinline__ void ldsm4(uint32_t r[4], uint32_t addr) {
    asm volatile("ldmatrix.sync.aligned.m8n8.x4.shared.b16 {%0,%1,%2,%3}, [%4];"
        : "=r"(r[0]), "=r"(r[1]), "=r"(r[2]), "=r"(r[3]) : "r"(addr));
}
__device__ __forceinline__ void mma_bf16(float c[4], const uint32_t a[4],
                                         uint32_t b0, uint32_t b1) {
    asm volatile(
        "mma.sync.aligned.m16n8k16.row.col.f32.bf16.bf16.f32 "
        "{%0,%1,%2,%3}, {%4,%5,%6,%7}, {%8,%9}, {%0,%1,%2,%3};"
        : "+f"(c[0]), "+f"(c[1]), "+f"(c[2]), "+f"(c[3])
        : "r"(a[0]), "r"(a[1]), "r"(a[2]), "r"(a[3]), "r"(b0), "r"(b1));
}
__device__ __forceinline__ void mma_f16(float c[4], const uint32_t a[4],
                                        uint32_t b0, uint32_t b1) {
    asm volatile(
        "mma.sync.aligned.m16n8k16.row.col.f32.f16.f16.f32 "
        "{%0,%1,%2,%3}, {%4,%5,%6,%7}, {%8,%9}, {%0,%1,%2,%3};"
        : "+f"(c[0]), "+f"(c[1]), "+f"(c[2]), "+f"(c[3])
        : "r"(a[0]), "r"(a[1]), "r"(a[2]), "r"(a[3]), "r"(b0), "r"(b1));
}
__device__ __forceinline__ void bf16_split(float v, __nv_bfloat16& hi, __nv_bfloat16& lo) {
    hi = __float2bfloat16(v);
    lo = __float2bfloat16(v - __bfloat162float(hi));
}
__device__ __forceinline__ uint32_t pack_h2(float a, float b) {
    __half2 h = __floats2half2_rn(a, b);
    return *(uint32_t*)&h;
}

// ------------------------- prep kernels -------------------------------------
__global__ __launch_bounds__(256) void convert_x_kernel(const float* __restrict__ x)
{
    int i = blockIdx.x * 256 + threadIdx.x;   // over MROWS*DMODEL/2
    float2 v = ((const float2*)x)[i];
    __nv_bfloat162 h, l;
    bf16_split(v.x, h.x, l.x);
    bf16_split(v.y, h.y, l.y);
    ((__nv_bfloat162*)g_xh)[i] = h;
    ((__nv_bfloat162*)g_xl)[i] = l;
}

// W_{Q,K,V}[h][k][e] -> g_Wh/g_Wl[(mat*1024 + h*64 + e)][k]  (z = mat*16+h)
__global__ __launch_bounds__(256) void transpose_wqkv(
    const float* __restrict__ Wq, const float* __restrict__ Wk,
    const float* __restrict__ Wv)
{
    const int z = blockIdx.z, mat = z >> 4, h = z & 15;
    const float* W = ((mat == 0) ? Wq : (mat == 1) ? Wk : Wv) + (size_t)h * DMODEL * DHEAD;
    __shared__ float t[32][33];
    const int k0 = blockIdx.x * 32, e0 = blockIdx.y * 32;
    const int tx = threadIdx.x & 31, ty = threadIdx.x >> 5;
    #pragma unroll
    for (int r = 0; r < 32; r += 8)
        t[ty + r][tx] = W[(size_t)(k0 + ty + r) * DHEAD + e0 + tx];
    __syncthreads();
    const int nbase = mat * 1024 + h * 64 + e0;
    #pragma unroll
    for (int r = 0; r < 32; r += 8) {
        float v = t[tx][ty + r];
        __nv_bfloat16 hi, lo; bf16_split(v, hi, lo);
        size_t idx = (size_t)(nbase + ty + r) * DMODEL + k0 + tx;
        g_Wh[idx] = hi; g_Wl[idx] = lo;
    }
}

// W_O flat [1024 c][1024 d] -> g_Woh/g_Wol[d][c]
__global__ __launch_bounds__(256) void transpose_wo(const float* __restrict__ Wo)
{
    __shared__ float t[32][33];
    const int d0 = blockIdx.x * 32, c0 = blockIdx.y * 32;
    const int tx = threadIdx.x & 31, ty = threadIdx.x >> 5;
    #pragma unroll
    for (int r = 0; r < 32; r += 8)
        t[ty + r][tx] = Wo[(size_t)(c0 + ty + r) * DMODEL + d0 + tx];
    __syncthreads();
    #pragma unroll
    for (int r = 0; r < 32; r += 8) {
        float v = t[tx][ty + r];
        __nv_bfloat16 hi, lo; bf16_split(v, hi, lo);
        size_t idx = (size_t)(d0 + ty + r) * DMODEL + c0 + tx;
        g_Woh[idx] = hi; g_Wol[idx] = lo;
    }
}

// ------------- plane-fused mma.sync bf16-split GEMM (cp.async+ldsm) ---------
// D = Ah·Bh^T + Al·Bh^T + Ah·Bl^T over K=1024, one k-chunk load feeds 3 planes.
// mode 0: QKV  (A = x-split, B = g_Wh/g_Wl [3072][1024]) -> g_Qf/g_Kf/g_Vt fp16
// mode 1: proj (A = Z-split, B = g_Woh/g_Wol)            -> outp fp32 + b_O
#define ASTR 40                         // bf16 per smem row (80B, phase-disjoint)
#define TILEB (128 * ASTR * 2)          // 10240 B per tile
#define GSMEM (8 * TILEB)               // 2 bufs x 4 tiles = 81920 B

__global__ __launch_bounds__(256) void gemm_kernel(
    const float* __restrict__ b0, const float* __restrict__ b1,
    const float* __restrict__ b2, float* __restrict__ outp, int mode)
{
    extern __shared__ __align__(16) char dsm[];
    const uint32_t sbase = smem_u32(dsm);
    // layout per buf: [Ah][Al][Bh][Bl]
    auto toff = [&](int buf, int t) -> uint32_t { return sbase + (buf * 4 + t) * TILEB; };

    const int tid = threadIdx.x, wid = tid >> 5, lane = tid & 31;
    const int m0 = blockIdx.y * 128, n0 = blockIdx.x * 128;
    const int wm = (wid & 3) * 32, wn = (wid >> 2) * 64;
    const int g  = lane >> 2;            // fragment row group
    const int kq = (lane & 3) * 2;       // fragment k-pair offset

    const __nv_bfloat16 *ah, *al, *bh, *bl;
    if (mode == 0) { ah = g_xh; al = g_xl; bh = g_Wh;  bl = g_Wl;  }
    else           { ah = g_Zh; al = g_Zl; bh = g_Woh; bl = g_Wol; }
    const int NC = 32;                   // 32 k-chunks of 32

    const int lr0 = tid >> 2, lseg = (tid & 3) * 8;   // loader row, k offset

    auto load_chunk = [&](int buf, int c) {
        const int k0 = c * 32;
        #pragma unroll
        for (int it = 0; it < 2; it++) {
            const int r = lr0 + it * 64;
            const uint32_t so = (r * ASTR + lseg) * 2;
            const size_t ga = (size_t)(m0 + r) * DMODEL + k0 + lseg;
            const size_t gb = (size_t)(n0 + r) * DMODEL + k0 + lseg;
            CP_ASYNC16(toff(buf, 0) + so, ah + ga);
            CP_ASYNC16(toff(buf, 1) + so, al + ga);
            CP_ASYNC16(toff(buf, 2) + so, bh + gb);
            CP_ASYNC16(toff(buf, 3) + so, bl + gb);
        }
        CP_COMMIT();
    };

    float C[2][8][4];
    #pragma unroll
    for (int i = 0; i < 2; i++)
        #pragma unroll
        for (int j = 0; j < 8; j++)
            #pragma unroll
            for (int q = 0; q < 4; q++) C[i][j][q] = 0.0f;

    // ldmatrix per-lane address pieces: row-in-16 = lane&15, k-half = (lane>>4)*8
    const int lrow = lane & 15, lcol = (lane >> 4) * 8;

    load_chunk(0, 0);

    for (int c = 0; c < NC; c++) {
        const int buf = c & 1;
        asm volatile("cp.async.wait_group 0;" ::: "memory");
        __syncthreads();                        // chunk c visible; buf^1 free
        if (c + 1 < NC) load_chunk(buf ^ 1, c + 1);

        #pragma unroll
        for (int ks = 0; ks < 2; ks++) {
            const uint32_t fo = (ks * 16 + lcol) * 2;   // frag k-byte offset
            uint32_t arh[2][4], brh[4][4], t[4][4];
            // Ah, Bh frags
            #pragma unroll
            for (int i = 0; i < 2; i++)
                ldsm4(arh[i], toff(buf, 0) + ((wm + i * 16 + lrow) * ASTR) * 2 + fo);
            #pragma unroll
            for (int j16 = 0; j16 < 4; j16++)
                ldsm4(brh[j16], toff(buf, 2) + ((wn + j16 * 16 + lrow) * ASTR) * 2 + fo);
            // plane 0: Ah·Bh
            #pragma unroll
            for (int i = 0; i < 2; i++)
                #pragma unroll
                for (int j = 0; j < 8; j++)
                    mma_bf16(C[i][j], arh[i], brh[j >> 1][j & 1], brh[j >> 1][(j & 1) + 2]);
            // plane 1: Al·Bh (t = Al frags)
            #pragma unroll
            for (int i = 0; i < 2; i++)
                ldsm4(t[i], toff(buf, 1) + ((wm + i * 16 + lrow) * ASTR) * 2 + fo);
            #pragma unroll
            for (int i = 0; i < 2; i++)
                #pragma unroll
                for (int j = 0; j < 8; j++)
                    mma_bf16(C[i][j], t[i], brh[j >> 1][j & 1], brh[j >> 1][(j & 1) + 2]);
            // plane 2: Ah·Bl (t = Bl frags)
            #pragma unroll
            for (int j16 = 0; j16 < 4; j16++)
                ldsm4(t[j16], toff(buf, 3) + ((wn + j16 * 16 + lrow) * ASTR) * 2 + fo);
            #pragma unroll
            for (int i = 0; i < 2; i++)
                #pragma unroll
                for (int j = 0; j < 8; j++)
                    mma_bf16(C[i][j], arh[i], t[j >> 1][j & 1], t[j >> 1][(j & 1) + 2]);
        }
        __syncthreads();
    }

    // ----- epilogue -----
    const int er = m0 + wm + g;
    const int ec = wn + kq;

    if (mode == 1) {
        #pragma unroll
        for (int i = 0; i < 2; i++) {
            #pragma unroll
            for (int j = 0; j < 8; j++) {
                const int col = n0 + ec + j * 8;
                const float bx = b0[col], by = b0[col + 1];
                const int row = er + i * 16;
                *(float2*)&outp[(size_t)row * DMODEL + col] =
                    make_float2(C[i][j][0] + bx, C[i][j][1] + by);
                *(float2*)&outp[(size_t)(row + 8) * DMODEL + col] =
                    make_float2(C[i][j][2] + bx, C[i][j][3] + by);
            }
        }
        return;
    }

    const int mat  = n0 >> 10;
    const int col0 = n0 & 1023;
    const float scale = (mat == 0) ? 0.125f : 1.0f;
    const float* bias = (mat == 0) ? b0 : (mat == 1) ? b1 : b2;

    #pragma unroll
    for (int i = 0; i < 2; i++) {
        #pragma unroll
        for (int j = 0; j < 8; j++) {
            const int col = col0 + ec + j * 8;
            const float bx = bias[col], by = bias[col + 1];
            const int row0 = er + i * 16, row1 = row0 + 8;
            const float v00 = (C[i][j][0] + bx) * scale;
            const float v01 = (C[i][j][1] + by) * scale;
            const float v10 = (C[i][j][2] + bx) * scale;
            const float v11 = (C[i][j][3] + by) * scale;
            if (mat == 0) {
                *(__half2*)&g_Qf[(size_t)row0 * DMODEL + col] = __floats2half2_rn(v00, v01);
                *(__half2*)&g_Qf[(size_t)row1 * DMODEL + col] = __floats2half2_rn(v10, v11);
            } else if (mat == 1) {
                *(__half2*)&g_Kf[(size_t)row0 * DMODEL + col] = __floats2half2_rn(v00, v01);
                *(__half2*)&g_Kf[(size_t)row1 * DMODEL + col] = __floats2half2_rn(v10, v11);
            } else {
                // V transposed: [(b*16+h)*64+e][seq]
                const int bb = row0 >> 11, s0 = row0 & 2047, s1 = s0 + 8;
                const int hh = col >> 6, e = col & 63;
                const size_t base = ((size_t)((bb * NHEADS + hh) * 64 + e)) * SEQ;
                g_Vt[base + s0]       = __float2half(v00);
                g_Vt[base + SEQ + s0] = __float2half(v01);   // e+1
                g_Vt[base + s1]       = __float2half(v10);
                g_Vt[base + SEQ + s1] = __float2half(v11);
            }
        }
    }
}

// ------------------------- fp16 mma flash attention -------------------------
// CTA = (qt, h, b): 64 queries, 4 warps x 16 rows. S and P live in fragments.
#define QSTR 72   // fp16 elems per smem row (36 words: conflict-free frag loads)

__global__ __launch_bounds__(128) void attn_kernel()
{
    __shared__ __align__(16) __half Qs[64 * QSTR];
    __shared__ __align__(16) __half Ks[64 * QSTR];
    __shared__ __align__(16) __half Vs[64 * QSTR];   // Vt tile: [d][key]

    const int qt = blockIdx.x, h = blockIdx.y, b = blockIdx.z;
    const int tid = threadIdx.x, w = tid >> 5, lane = tid & 31;
    const int g = lane >> 2, kq = (lane & 3) * 2;
    const int q0 = qt * 64;

    // Q tile load: 64 rows x 8 16B-segs = 512 slots
    #pragma unroll
    for (int it = 0; it < 4; it++) {
        const int s = tid + it * 128, r = s >> 3, seg = s & 7;
        *(uint4*)&Qs[r * QSTR + seg * 8] =
            *(const uint4*)(g_Qf + (size_t)(b * SEQ + q0 + r) * DMODEL + h * 64 + seg * 8);
    }

    uint4 kvr[4], vvr[4];
    auto load_regs = [&](int kt) {
        const int k0 = kt * 64;
        #pragma unroll
        for (int it = 0; it < 4; it++) {
            const int s = tid + it * 128, r = s >> 3, seg = s & 7;
            kvr[it] = *(const uint4*)(g_Kf + (size_t)(b * SEQ + k0 + r) * DMODEL + h * 64 + seg * 8);
            vvr[it] = *(const uint4*)(g_Vt + ((size_t)((b * NHEADS + h) * 64 + r)) * SEQ + k0 + seg * 8);
        }
    };
    auto store_smem = [&]() {
        #pragma unroll
        for (int it = 0; it < 4; it++) {
            const int s = tid + it * 128, r = s >> 3, seg = s & 7;
            *(uint4*)&Ks[r * QSTR + seg * 8] = kvr[it];
            *(uint4*)&Vs[r * QSTR + seg * 8] = vvr[it];
        }
    };

    float m_run[2] = {-1e30f, -1e30f};
    float l_run[2] = {0.0f, 0.0f};
    float Z[8][4];
    #pragma unroll
    for (int j = 0; j < 8; j++)
        #pragma unroll
        for (int q = 0; q < 4; q++) Z[j][q] = 0.0f;

    load_regs(0);

    for (int kt = 0; kt <= qt; kt++) {
        store_smem();
        __syncthreads();
        if (kt < qt) load_regs(kt + 1);

        // ---- S = Q K^T ----
        float S[8][4];
        #pragma unroll
        for (int j = 0; j < 8; j++)
            #pragma unroll
            for (int q = 0; q < 4; q++) S[j][q] = 0.0f;

        #pragma unroll
        for (int ks = 0; ks < 4; ks++) {
            const int kc = ks * 16 + kq;
            const int row = w * 16 + g;
            uint32_t a[4];
            a[0] = *(const uint32_t*)&Qs[(row)     * QSTR + kc];
            a[1] = *(const uint32_t*)&Qs[(row + 8) * QSTR + kc];
            a[2] = *(const uint32_t*)&Qs[(row)     * QSTR + kc + 8];
            a[3] = *(const uint32_t*)&Qs[(row + 8) * QSTR + kc + 8];
            #pragma unroll
            for (int j = 0; j < 8; j++) {
                const int nrow = j * 8 + g;
                const uint32_t bb0 = *(const uint32_t*)&Ks[nrow * QSTR + kc];
                const uint32_t bb1 = *(const uint32_t*)&Ks[nrow * QSTR + kc + 8];
                mma_f16(S[j], a, bb0, bb1);
            }
        }

        // ---- causal mask (diagonal tile only) ----
        if (kt == qt) {
            const int r0 = w * 16 + g, r1 = r0 + 8;
            #pragma unroll
            for (int j = 0; j < 8; j++) {
                const int c0 = j * 8 + kq, c1 = c0 + 1;
                if (c0 > r0) S[j][0] = -1e30f;
                if (c1 > r0) S[j][1] = -1e30f;
                if (c0 > r1) S[j][2] = -1e30f;
                if (c1 > r1) S[j][3] = -1e30f;
            }
        }

        // ---- online softmax on fragments (rows r0, r1 per thread) ----
        float mx0 = -1e30f, mx1 = -1e30f;
        #pragma unroll
        for (int j = 0; j < 8; j++) {
            mx0 = fmaxf(mx0, fmaxf(S[j][0], S[j][1]));
            mx1 = fmaxf(mx1, fmaxf(S[j][2], S[j][3]));
        }
        mx0 = fmaxf(mx0, __shfl_xor_sync(0xffffffffu, mx0, 1));
        mx0 = fmaxf(mx0, __shfl_xor_sync(0xffffffffu, mx0, 2));
        mx1 = fmaxf(mx1, __shfl_xor_sync(0xffffffffu, mx1, 1));
        mx1 = fmaxf(mx1, __shfl_xor_sync(0xffffffffu, mx1, 2));

        const float mn0 = fmaxf(m_run[0], mx0);
        const float mn1 = fmaxf(m_run[1], mx1);
        const float al0 = __expf(m_run[0] - mn0);
        const float al1 = __expf(m_run[1] - mn1);
        float sum0 = 0.0f, sum1 = 0.0f;
        #pragma unroll
        for (int j = 0; j < 8; j++) {
            S[j][0] = __expf(S[j][0] - mn0); sum0 += S[j][0];
            S[j][1] = __expf(S[j][1] - mn0); sum0 += S[j][1];
            S[j][2] = __expf(S[j][2] - mn1); sum1 += S[j][2];
            S[j][3] = __expf(S[j][3] - mn1); sum1 += S[j][3];
        }
        sum0 += __shfl_xor_sync(0xffffffffu, sum0, 1);
        sum0 += __shfl_xor_sync(0xffffffffu, sum0, 2);
        sum1 += __shfl_xor_sync(0xffffffffu, sum1, 1);
        sum1 += __shfl_xor_sync(0xffffffffu, sum1, 2);

        l_run[0] = l_run[0] * al0 + sum0;  m_run[0] = mn0;
        l_run[1] = l_run[1] * al1 + sum1;  m_run[1] = mn1;

        #pragma unroll
        for (int j = 0; j < 8; j++) {
            Z[j][0] *= al0; Z[j][1] *= al0;
            Z[j][2] *= al1; Z[j][3] *= al1;
        }

        // ---- Z += P V : repack S c-frags into a-frags (pure register) ----
        #pragma unroll
        for (int jj = 0; jj < 4; jj++) {
            uint32_t a[4];
            a[0] = pack_h2(S[2*jj][0],     S[2*jj][1]);
            a[1] = pack_h2(S[2*jj][2],     S[2*jj][3]);
            a[2] = pack_h2(S[2*jj + 1][0], S[2*jj + 1][1]);
            a[3] = pack_h2(S[2*jj + 1][2], S[2*jj + 1][3]);
            const int kc = jj * 16 + kq;
            #pragma unroll
            for (int j = 0; j < 8; j++) {
                const int nrow = j * 8 + g;
                const uint32_t bb0 = *(const uint32_t*)&Vs[nrow * QSTR + kc];
                const uint32_t bb1 = *(const uint32_t*)&Vs[nrow * QSTR + kc + 8];
                mma_f16(Z[j], a, bb0, bb1);
            }
        }
        __syncthreads();
    }

    // ---- epilogue: normalize + split-bf16 Z ----
    const float inv0 = 1.0f / l_run[0];
    const float inv1 = 1.0f / l_run[1];
    const int r0 = q0 + w * 16 + g, r1 = r0 + 8;
    #pragma unroll
    for (int j = 0; j < 8; j++) {
        const int col = h * 64 + j * 8 + kq;
        const size_t i0 = (size_t)(b * SEQ + r0) * DMODEL + col;
        const size_t i1 = (size_t)(b * SEQ + r1) * DMODEL + col;
        __nv_bfloat16 hi, lo;
        bf16_split(Z[j][0] * inv0, hi, lo); g_Zh[i0]     = hi; g_Zl[i0]     = lo;
        bf16_split(Z[j][1] * inv0, hi, lo); g_Zh[i0 + 1] = hi; g_Zl[i0 + 1] = lo;
        bf16_split(Z[j][2] * inv1, hi, lo); g_Zh[i1]     = hi; g_Zl[i1]     = lo;
        bf16_split(Z[j][3] * inv1, hi, lo); g_Zh[i1 + 1] = hi; g_Zl[i1 + 1] = lo;
    }
}

// ------------------------------ launch --------------------------------------
extern "C" void kernel_launch(void* const* d_in, const int* in_sizes, int n_in,
                              void* d_out, int out_size)
{
    (void)in_sizes; (void)n_in; (void)out_size;
    const float* x  = (const float*)d_in[0];
    const float* Wq = (const float*)d_in[1];
    const float* Wk = (const float*)d_in[2];
    const float* Wv = (const float*)d_in[3];
    const float* Wo = (const float*)d_in[4];
    const float* bq = (const float*)d_in[5];
    const float* bk = (const float*)d_in[6];
    const float* bv = (const float*)d_in[7];
    const float* bo = (const float*)d_in[8];
    float* out = (float*)d_out;

    cudaFuncSetAttribute(gemm_kernel,
                         cudaFuncAttributeMaxDynamicSharedMemorySize, GSMEM);

    convert_x_kernel<<<(MROWS * DMODEL / 2) / 256, 256>>>(x);
    transpose_wqkv<<<dim3(32, 2, 48), 256>>>(Wq, Wk, Wv);
    transpose_wo<<<dim3(32, 32), 256>>>(Wo);

    gemm_kernel<<<dim3(24, 32), 256, GSMEM>>>(bq, bk, bv, nullptr, 0);

    attn_kernel<<<dim3(SEQ / 64, NHEADS, BATCH), 128>>>();

    gemm_kernel<<<dim3(8, 32), 256, GSMEM>>>(bo, bo, bo, out, 1);
}